// round 5
// baseline (speedup 1.0000x reference)
#include <cuda_runtime.h>
#include <cuda_bf16.h>
#include <math.h>

#define BQ 2
#define S_LEN 2048
#define HK 16
#define HV 32
#define DK 128
#define DV 128
#define QKV 8192
#define NROWS (BQ * S_LEN)

typedef unsigned long long ull;

// ---------------- scratch (device globals; no runtime allocation) ----------------
__device__ float g_qn[(size_t)NROWS * HK * DK];    // l2norm(q) * scale
__device__ float g_kn[(size_t)NROWS * HK * DK];    // l2norm(k)
__device__ float g_v [(size_t)NROWS * HV * DV];
__device__ float g_gate[(size_t)NROWS * HV * 2];   // float2 per (row,h): eg, beta

// ---------------- packed f32x2 helpers ----------------
__device__ __forceinline__ ull pack2(float lo, float hi) {
    ull r;
    asm("mov.b64 %0, {%1,%2};" : "=l"(r) : "f"(lo), "f"(hi));
    return r;
}
__device__ __forceinline__ float2 unpack2(ull v) {
    float2 r;
    asm("mov.b64 {%0,%1}, %2;" : "=f"(r.x), "=f"(r.y) : "l"(v));
    return r;
}
#define FMA2(d, a, b, c) asm("fma.rn.f32x2 %0, %1, %2, %3;" : "=l"(d) : "l"(a), "l"(b), "l"(c))
#define MUL2(d, a, b)    asm("mul.rn.f32x2 %0, %1, %2;"     : "=l"(d) : "l"(a), "l"(b))
#define ADD2(d, a, b)    asm("add.rn.f32x2 %0, %1, %2;"     : "=l"(d) : "l"(a), "l"(b))

union F4U { float4 f; ull u[2]; };

// ---------------- kernel 1: conv + silu + l2norm + gating ----------------
__global__ __launch_bounds__(256) void prep_kernel(
    const float* __restrict__ x,      // [NROWS, QKV]
    const float* __restrict__ bvec,   // [NROWS, HV]
    const float* __restrict__ avec,   // [NROWS, HV]
    const float* __restrict__ w,      // [QKV, 4]
    const float* __restrict__ dt_bias,// [HV]
    const float* __restrict__ alog)   // [HV]
{
    const int row = blockIdx.x;
    const int s   = row & (S_LEN - 1);
    const int tid = threadIdx.x;

    __shared__ float ysm[QKV];            // 32 KB

    const float4* w4 = (const float4*)w;  // taps contiguous per channel

    // --- causal depthwise conv (width 4) + SiLU ---
    for (int base = tid * 4; base < QKV; base += 256 * 4) {
        float4 wv0 = __ldg(w4 + base + 0);
        float4 wv1 = __ldg(w4 + base + 1);
        float4 wv2 = __ldg(w4 + base + 2);
        float4 wv3 = __ldg(w4 + base + 3);
        const float* t0 = (const float*)&wv0;
        const float* t1 = (const float*)&wv1;
        const float* t2 = (const float*)&wv2;
        const float* t3 = (const float*)&wv3;
        float4 acc = make_float4(0.f, 0.f, 0.f, 0.f);
#pragma unroll
        for (int j = 0; j < 4; j++) {
            if (s - 3 + j >= 0) {
                const float4 xv = *reinterpret_cast<const float4*>(
                    x + (size_t)(row - 3 + j) * QKV + base);
                acc.x = fmaf(xv.x, t0[j], acc.x);
                acc.y = fmaf(xv.y, t1[j], acc.y);
                acc.z = fmaf(xv.z, t2[j], acc.z);
                acc.w = fmaf(xv.w, t3[j], acc.w);
            }
        }
        acc.x = acc.x / (1.f + __expf(-acc.x));
        acc.y = acc.y / (1.f + __expf(-acc.y));
        acc.z = acc.z / (1.f + __expf(-acc.z));
        acc.w = acc.w / (1.f + __expf(-acc.w));
        *reinterpret_cast<float4*>(ysm + base) = acc;
    }
    __syncthreads();

    const int wi   = tid >> 5;
    const int lane = tid & 31;
    const float qscale = 0.08838834764831845f; // 128^-0.5

    // --- l2 norms for 32 groups (16 q heads + 16 k heads) ---
    for (int gr = wi; gr < 32; gr += 8) {
        const float4 v4 = reinterpret_cast<const float4*>(ysm + gr * 128)[lane];
        float ss = v4.x * v4.x + v4.y * v4.y + v4.z * v4.z + v4.w * v4.w;
#pragma unroll
        for (int o = 16; o > 0; o >>= 1) ss += __shfl_xor_sync(0xffffffffu, ss, o);
        const bool isq = gr < 16;
        const float mul = rsqrtf(ss + 1e-6f) * (isq ? qscale : 1.f);
        float4 ov = make_float4(v4.x * mul, v4.y * mul, v4.z * mul, v4.w * mul);
        if (isq)
            reinterpret_cast<float4*>(g_qn + ((size_t)row * HK + gr) * DK)[lane] = ov;
        else
            reinterpret_cast<float4*>(g_kn + ((size_t)row * HK + (gr - 16)) * DK)[lane] = ov;
    }

    // --- v copy ---
    for (int i = tid * 4; i < HV * DV; i += 256 * 4)
        *reinterpret_cast<float4*>(g_v + (size_t)row * (HV * DV) + i) =
            *reinterpret_cast<const float4*>(ysm + 2 * HK * DK + i);

    // --- gating table (eg, beta) ---
    if (tid < HV) {
        const int h = tid;
        float aa = avec[(size_t)row * HV + h] + dt_bias[h];
        float sp = (aa > 20.f) ? aa : log1pf(expf(aa));
        float g  = -expf(alog[h]) * sp;
        float eg = expf(g);
        float bb = bvec[(size_t)row * HV + h];
        float beta = 1.f / (1.f + expf(-bb));
        *reinterpret_cast<float2*>(g_gate + ((size_t)row * HV + h) * 2) =
            make_float2(eg, beta);
    }
}

// ---------------- kernel 2: gated delta-rule recurrence ----------------
// grid 128 = (b, h, vh). 256 threads = 8 INDEPENDENT warps, each owning 8
// v-columns (warp w -> cols vh*64 + w*8 .. +8). NO block barriers.
// Within a warp: lane = (c, p), c = lane>>2 chain 0..7, p = lane&3 k-slice of 32.
// Each warp stages k/q in its own 4-slot smem ring (coalesced LDG.128 ->
// STS.128 -> padded conflict-free LDS.128). v/gates in depth-4 register pipes.
// Software pipeline: LDG t+6 (2 reg sets in flight), STS t+4, consume t.
__global__ __launch_bounds__(256, 1) void rec_kernel(float* __restrict__ out)
{
    const int blk = blockIdx.x;
    const int b   = blk >> 6;
    const int h   = (blk >> 1) & 31;
    const int vh  = blk & 1;
    const int hk  = h >> 1;

    const int tid  = threadIdx.x;
    const int w    = tid >> 5;
    const int lane = tid & 31;
    const int c    = lane >> 2;        // chain 0..7
    const int p    = lane & 3;         // k-slice 0..3 (32 dims)

    // per-warp ring: [slot 0..3][k=0/q=1][4 groups x 40 floats padded]
    __shared__ float skq[8][4][2][160];

    // STS layout: lane l writes floats [4l..4l+4) of the row at
    // group (l>>3), offset (l&7)*4  -> each 8-lane phase hits distinct banks.
    const int sts_off = (lane >> 3) * 40 + (lane & 7) * 4;

    ull st[16];
#pragma unroll
    for (int i = 0; i < 16; i++) st[i] = 0ull;

    const float* kbase = g_kn + ((size_t)(b * S_LEN) * HK + hk) * DK;
    const float* qbase = g_qn + ((size_t)(b * S_LEN) * HK + hk) * DK;
    const int col = vh * 64 + w * 8 + c;
    const float* vptr = g_v    + ((size_t)(b * S_LEN) * HV + h) * DV + col;
    const float* gptr = g_gate + ((size_t)(b * S_LEN) * HV + h) * 2;
    float*       optr = out    + ((size_t)(b * S_LEN) * HV + h) * DV + col;
    const size_t qk_stride = (size_t)HK * DK;
    const size_t v_stride  = (size_t)HV * DV;
    const size_t g_stride  = (size_t)HV * 2;

    // ---- prologue: fill slots 0..3, v/g pipe 0..3, LDG sets for tokens 4,5 ----
    F4U kin[2], qin[2];
    float  vbuf[4];
    float2 gbuf[4];

#pragma unroll
    for (int j = 0; j < 4; j++) {
        F4U kt, qt;
        kt.f = __ldg((const float4*)(kbase + (size_t)j * qk_stride) + lane);
        qt.f = __ldg((const float4*)(qbase + (size_t)j * qk_stride) + lane);
        *reinterpret_cast<float4*>(&skq[w][j][0][sts_off]) = kt.f;
        *reinterpret_cast<float4*>(&skq[w][j][1][sts_off]) = qt.f;
        vbuf[j] = __ldg(vptr + (size_t)j * v_stride);
        gbuf[j] = *reinterpret_cast<const float2*>(gptr + (size_t)j * g_stride);
    }
    kin[0].f = __ldg((const float4*)(kbase + (size_t)4 * qk_stride) + lane);
    qin[0].f = __ldg((const float4*)(qbase + (size_t)4 * qk_stride) + lane);
    kin[1].f = __ldg((const float4*)(kbase + (size_t)5 * qk_stride) + lane);
    qin[1].f = __ldg((const float4*)(qbase + (size_t)5 * qk_stride) + lane);
    __syncwarp();

#pragma unroll 1
    for (int t0 = 0; t0 < S_LEN; t0 += 4) {
#pragma unroll
        for (int j = 0; j < 4; j++) {
            const int t = t0 + j;
            const float eg = gbuf[j].x, beta = gbuf[j].y;
            const ull egp = pack2(eg, eg);

            // k slice for this token (slot j)
            F4U kr[8];
            const float* kp = &skq[w][j][0][p * 40];
#pragma unroll
            for (int i = 0; i < 8; i++)
                kr[i].f = *reinterpret_cast<const float4*>(kp + i * 4);

            // pred on PRE-decay state (eg applied as scalar after reduction)
            ull pr0 = 0, pr1 = 0, pr2 = 0, pr3 = 0;
#pragma unroll
            for (int i = 0; i < 4; i++) {
                FMA2(pr0, kr[2*i].u[0],   st[4*i+0], pr0);
                FMA2(pr1, kr[2*i].u[1],   st[4*i+1], pr1);
                FMA2(pr2, kr[2*i+1].u[0], st[4*i+2], pr2);
                FMA2(pr3, kr[2*i+1].u[1], st[4*i+3], pr3);
            }
            // decay (off the pred critical path)
#pragma unroll
            for (int i = 0; i < 16; i++) MUL2(st[i], st[i], egp);

            ull prA, prB, prC;
            ADD2(prA, pr0, pr1);
            ADD2(prB, pr2, pr3);
            ADD2(prC, prA, prB);
            float2 pf = unpack2(prC);
            float pred = pf.x + pf.y;
            pred += __shfl_xor_sync(0xffffffffu, pred, 1);
            pred += __shfl_xor_sync(0xffffffffu, pred, 2);
            pred *= eg;

            const float u = beta * (vbuf[j] - pred);
            const ull up = pack2(u, u);

            // state update (unblocks next token's recurrence)
#pragma unroll
            for (int i = 0; i < 8; i++) {
                FMA2(st[2*i],   kr[i].u[0], up, st[2*i]);
                FMA2(st[2*i+1], kr[i].u[1], up, st[2*i+1]);
            }

            // q slice (last read of slot j)
            F4U qr[8];
            const float* qp = &skq[w][j][1][p * 40];
#pragma unroll
            for (int i = 0; i < 8; i++)
                qr[i].f = *reinterpret_cast<const float4*>(qp + i * 4);

            __syncwarp();

            // STS token t+4 into slot j (from in-flight set j&1)
            {
                *reinterpret_cast<float4*>(&skq[w][j][0][sts_off]) = kin[j & 1].f;
                *reinterpret_cast<float4*>(&skq[w][j][1][sts_off]) = qin[j & 1].f;
            }
            // LDG token t+6 into the set just freed
            {
                int tl = t + 6; if (tl > S_LEN - 1) tl = S_LEN - 1;
                kin[j & 1].f = __ldg((const float4*)(kbase + (size_t)tl * qk_stride) + lane);
                qin[j & 1].f = __ldg((const float4*)(qbase + (size_t)tl * qk_stride) + lane);
            }
            // v/g prefetch token t+4
            {
                int tn = t + 4; if (tn > S_LEN - 1) tn = S_LEN - 1;
                vbuf[j] = __ldg(vptr + (size_t)tn * v_stride);
                gbuf[j] = *reinterpret_cast<const float2*>(gptr + (size_t)tn * g_stride);
            }

            // output: o = q . S_post (off the recurrence critical path)
            ull qs0 = 0, qs1 = 0, qs2 = 0, qs3 = 0;
#pragma unroll
            for (int i = 0; i < 4; i++) {
                FMA2(qs0, qr[2*i].u[0],   st[4*i+0], qs0);
                FMA2(qs1, qr[2*i].u[1],   st[4*i+1], qs1);
                FMA2(qs2, qr[2*i+1].u[0], st[4*i+2], qs2);
                FMA2(qs3, qr[2*i+1].u[1], st[4*i+3], qs3);
            }
            ull qsA, qsB, qsC;
            ADD2(qsA, qs0, qs1);
            ADD2(qsB, qs2, qs3);
            ADD2(qsC, qsA, qsB);
            float2 qf = unpack2(qsC);
            float oo = qf.x + qf.y;
            oo += __shfl_xor_sync(0xffffffffu, oo, 1);
            oo += __shfl_xor_sync(0xffffffffu, oo, 2);

            if (p == 0) optr[(size_t)t * v_stride] = oo;
        }
    }
}

// ---------------- launch ----------------
extern "C" void kernel_launch(void* const* d_in, const int* in_sizes, int n_in,
                              void* d_out, int out_size)
{
    const float* mixed_qkv = (const float*)d_in[0];
    const float* bvec      = (const float*)d_in[1];
    const float* avec      = (const float*)d_in[2];
    const float* convw     = (const float*)d_in[3];
    const float* dt_bias   = (const float*)d_in[4];
    const float* alog      = (const float*)d_in[5];
    float* out = (float*)d_out;

    prep_kernel<<<NROWS, 256>>>(mixed_qkv, bvec, avec, convw, dt_bias, alog);
    rec_kernel<<<BQ * HV * 2, 256>>>(out);
}

// round 6
// speedup vs baseline: 1.1930x; 1.1930x over previous
#include <cuda_runtime.h>
#include <cuda_bf16.h>
#include <math.h>

#define BQ 2
#define S_LEN 2048
#define HK 16
#define HV 32
#define DK 128
#define DV 128
#define QKV 8192
#define NROWS (BQ * S_LEN)
#define TB 16   // tokens per smem staging batch

typedef unsigned long long ull;

// ---------------- scratch (device globals; no runtime allocation) ----------------
__device__ float g_qn[(size_t)NROWS * HK * DK];    // l2norm(q) * scale
__device__ float g_kn[(size_t)NROWS * HK * DK];    // l2norm(k)
__device__ float g_v [(size_t)NROWS * HV * DV];
__device__ float g_gate[(size_t)NROWS * HV * 2];   // float2 per (row,h): eg, beta

// ---------------- packed f32x2 helpers ----------------
__device__ __forceinline__ ull pack2(float lo, float hi) {
    ull r;
    asm("mov.b64 %0, {%1,%2};" : "=l"(r) : "f"(lo), "f"(hi));
    return r;
}
__device__ __forceinline__ float2 unpack2(ull v) {
    float2 r;
    asm("mov.b64 {%0,%1}, %2;" : "=f"(r.x), "=f"(r.y) : "l"(v));
    return r;
}
#define FMA2(d, a, b, c) asm("fma.rn.f32x2 %0, %1, %2, %3;" : "=l"(d) : "l"(a), "l"(b), "l"(c))
#define MUL2(d, a, b)    asm("mul.rn.f32x2 %0, %1, %2;"     : "=l"(d) : "l"(a), "l"(b))
#define ADD2(d, a, b)    asm("add.rn.f32x2 %0, %1, %2;"     : "=l"(d) : "l"(a), "l"(b))

union F4U { float4 f; ull u[2]; };

// ---------------- kernel 1: conv + silu + l2norm + gating ----------------
__global__ __launch_bounds__(256) void prep_kernel(
    const float* __restrict__ x,      // [NROWS, QKV]
    const float* __restrict__ bvec,   // [NROWS, HV]
    const float* __restrict__ avec,   // [NROWS, HV]
    const float* __restrict__ w,      // [QKV, 4]
    const float* __restrict__ dt_bias,// [HV]
    const float* __restrict__ alog)   // [HV]
{
    const int row = blockIdx.x;
    const int s   = row & (S_LEN - 1);
    const int tid = threadIdx.x;

    __shared__ float ysm[QKV];            // 32 KB

    const float4* w4 = (const float4*)w;  // taps contiguous per channel

    // --- causal depthwise conv (width 4) + SiLU ---
    for (int base = tid * 4; base < QKV; base += 256 * 4) {
        float4 wv0 = __ldg(w4 + base + 0);
        float4 wv1 = __ldg(w4 + base + 1);
        float4 wv2 = __ldg(w4 + base + 2);
        float4 wv3 = __ldg(w4 + base + 3);
        const float* t0 = (const float*)&wv0;
        const float* t1 = (const float*)&wv1;
        const float* t2 = (const float*)&wv2;
        const float* t3 = (const float*)&wv3;
        float4 acc = make_float4(0.f, 0.f, 0.f, 0.f);
#pragma unroll
        for (int j = 0; j < 4; j++) {
            if (s - 3 + j >= 0) {
                const float4 xv = *reinterpret_cast<const float4*>(
                    x + (size_t)(row - 3 + j) * QKV + base);
                acc.x = fmaf(xv.x, t0[j], acc.x);
                acc.y = fmaf(xv.y, t1[j], acc.y);
                acc.z = fmaf(xv.z, t2[j], acc.z);
                acc.w = fmaf(xv.w, t3[j], acc.w);
            }
        }
        acc.x = acc.x / (1.f + __expf(-acc.x));
        acc.y = acc.y / (1.f + __expf(-acc.y));
        acc.z = acc.z / (1.f + __expf(-acc.z));
        acc.w = acc.w / (1.f + __expf(-acc.w));
        *reinterpret_cast<float4*>(ysm + base) = acc;
    }
    __syncthreads();

    const int wi   = tid >> 5;
    const int lane = tid & 31;
    const float qscale = 0.08838834764831845f; // 128^-0.5

    // --- l2 norms for 32 groups (16 q heads + 16 k heads) ---
    for (int gr = wi; gr < 32; gr += 8) {
        const float4 v4 = reinterpret_cast<const float4*>(ysm + gr * 128)[lane];
        float ss = v4.x * v4.x + v4.y * v4.y + v4.z * v4.z + v4.w * v4.w;
#pragma unroll
        for (int o = 16; o > 0; o >>= 1) ss += __shfl_xor_sync(0xffffffffu, ss, o);
        const bool isq = gr < 16;
        const float mul = rsqrtf(ss + 1e-6f) * (isq ? qscale : 1.f);
        float4 ov = make_float4(v4.x * mul, v4.y * mul, v4.z * mul, v4.w * mul);
        if (isq)
            reinterpret_cast<float4*>(g_qn + ((size_t)row * HK + gr) * DK)[lane] = ov;
        else
            reinterpret_cast<float4*>(g_kn + ((size_t)row * HK + (gr - 16)) * DK)[lane] = ov;
    }

    // --- v copy ---
    for (int i = tid * 4; i < HV * DV; i += 256 * 4)
        *reinterpret_cast<float4*>(g_v + (size_t)row * (HV * DV) + i) =
            *reinterpret_cast<const float4*>(ysm + 2 * HK * DK + i);

    // --- gating table (eg, beta) ---
    if (tid < HV) {
        const int h = tid;
        float aa = avec[(size_t)row * HV + h] + dt_bias[h];
        float sp = (aa > 20.f) ? aa : log1pf(expf(aa));
        float g  = -expf(alog[h]) * sp;
        float eg = expf(g);
        float bb = bvec[(size_t)row * HV + h];
        float beta = 1.f / (1.f + expf(-bb));
        *reinterpret_cast<float2*>(g_gate + ((size_t)row * HV + h) * 2) =
            make_float2(eg, beta);
    }
}

// ---------------- kernel 2: gated delta-rule recurrence ----------------
// grid 128 = (b, h, vh). 512 threads = 64 chains x 8 k-slices of 16 dims.
// Thread (c, p): state S[16p..16p+16, col] as 8 packed f32x2 (c = tid>>3, p = tid&7).
// Block-cooperative double-buffered smem staging (one barrier per 16 tokens).
// k/q rows stored as 8 groups of 16 floats padded to 20 -> the 8 p-lanes' LDS.128
// hit all 32 banks exactly once (4-way c-broadcast): conflict-free.
// Per token: pred on pre-decay state (eg folded in after reduction) -> 3 shfl ->
// u -> update (unblocks next token) -> qsum on post state -> 3 shfl -> store.
__global__ __launch_bounds__(512, 1) void rec_kernel(float* __restrict__ out)
{
    const int blk = blockIdx.x;
    const int b   = blk >> 6;
    const int h   = (blk >> 1) & 31;
    const int vh  = blk & 1;
    const int hk  = h >> 1;

    const int tid = threadIdx.x;
    const int c   = tid >> 3;          // chain 0..63
    const int p   = tid & 7;           // k-slice 0..7 (16 dims)

    __shared__ float skq[2][TB][2][160];   // [buf][token][k=0/q=1][8 groups x 20]
    __shared__ float sv[2][TB][64];
    __shared__ float2 sg[2][TB];

    ull st[8];
#pragma unroll
    for (int i = 0; i < 8; i++) st[i] = 0ull;

    const float* kbase = g_kn + ((size_t)(b * S_LEN) * HK + hk) * DK;
    const float* qbase = g_qn + ((size_t)(b * S_LEN) * HK + hk) * DK;
    const float* vbase = g_v  + ((size_t)(b * S_LEN) * HV + h) * DV + vh * 64;
    const float* gbase = g_gate + ((size_t)(b * S_LEN) * HV + h) * 2;
    const size_t qk_stride = (size_t)HK * DK;
    const size_t v_stride  = (size_t)HV * DV;

    auto load_batch = [&](int buf, int t0) {
        // k and q: TB tokens x 32 float4 chunks each; 512 threads -> 1 round each
        {
            int tt = tid >> 5, j = tid & 31;
            int off = (j >> 2) * 20 + (j & 3) * 4;
            float4 kv = __ldg((const float4*)(kbase + (size_t)(t0 + tt) * qk_stride) + j);
            *reinterpret_cast<float4*>(&skq[buf][tt][0][off]) = kv;
            float4 qv = __ldg((const float4*)(qbase + (size_t)(t0 + tt) * qk_stride) + j);
            *reinterpret_cast<float4*>(&skq[buf][tt][1][off]) = qv;
        }
        // v: TB x 16 float4 = 256
        if (tid < 256) {
            int tt = tid >> 4, j = tid & 15;
            *reinterpret_cast<float4*>(&sv[buf][tt][j * 4]) =
                __ldg((const float4*)(vbase + (size_t)(t0 + tt) * v_stride) + j);
        }
        if (tid < TB)
            sg[buf][tid] = *reinterpret_cast<const float2*>(
                gbase + (size_t)(t0 + tid) * (HV * 2));
    };

    load_batch(0, 0);
    __syncthreads();
    int buf = 0;

    float* obase = out + ((size_t)(b * S_LEN) * HV + h) * DV + vh * 64 + c;

#pragma unroll 1
    for (int t0 = 0; t0 < S_LEN; t0 += TB) {
        if (t0 + TB < S_LEN) load_batch(buf ^ 1, t0 + TB);

#pragma unroll 1
        for (int tt = 0; tt < TB; tt++) {
            const float2 g2 = sg[buf][tt];
            const float eg = g2.x, beta = g2.y;

            // k slice: 16 floats = 4 float4
            F4U kr[4];
            const float* kp = &skq[buf][tt][0][p * 20];
#pragma unroll
            for (int i = 0; i < 4; i++)
                kr[i].f = *reinterpret_cast<const float4*>(kp + i * 4);

            // pred on PRE-decay state (4 accumulators, depth 2)
            ull pr0 = 0, pr1 = 0, pr2 = 0, pr3 = 0;
            FMA2(pr0, kr[0].u[0], st[0], pr0);
            FMA2(pr1, kr[0].u[1], st[1], pr1);
            FMA2(pr2, kr[1].u[0], st[2], pr2);
            FMA2(pr3, kr[1].u[1], st[3], pr3);
            FMA2(pr0, kr[2].u[0], st[4], pr0);
            FMA2(pr1, kr[2].u[1], st[5], pr1);
            FMA2(pr2, kr[3].u[0], st[6], pr2);
            FMA2(pr3, kr[3].u[1], st[7], pr3);

            // decay (off the pred critical path)
            const ull egp = pack2(eg, eg);
#pragma unroll
            for (int i = 0; i < 8; i++) MUL2(st[i], st[i], egp);

            ull prA, prB, prC;
            ADD2(prA, pr0, pr1);
            ADD2(prB, pr2, pr3);
            ADD2(prC, prA, prB);
            float2 pf = unpack2(prC);
            float pred = pf.x + pf.y;
            pred += __shfl_xor_sync(0xffffffffu, pred, 1);
            pred += __shfl_xor_sync(0xffffffffu, pred, 2);
            pred += __shfl_xor_sync(0xffffffffu, pred, 4);
            pred *= eg;

            const float u = beta * (sv[buf][tt][c] - pred);
            const ull up = pack2(u, u);

            // state update (unblocks next token's recurrence)
#pragma unroll
            for (int i = 0; i < 4; i++) {
                FMA2(st[2*i],   kr[i].u[0], up, st[2*i]);
                FMA2(st[2*i+1], kr[i].u[1], up, st[2*i+1]);
            }

            // q slice + output (off the recurrence critical path)
            F4U qr[4];
            const float* qp = &skq[buf][tt][1][p * 20];
#pragma unroll
            for (int i = 0; i < 4; i++)
                qr[i].f = *reinterpret_cast<const float4*>(qp + i * 4);

            ull qs0 = 0, qs1 = 0, qs2 = 0, qs3 = 0;
            FMA2(qs0, qr[0].u[0], st[0], qs0);
            FMA2(qs1, qr[0].u[1], st[1], qs1);
            FMA2(qs2, qr[1].u[0], st[2], qs2);
            FMA2(qs3, qr[1].u[1], st[3], qs3);
            FMA2(qs0, qr[2].u[0], st[4], qs0);
            FMA2(qs1, qr[2].u[1], st[5], qs1);
            FMA2(qs2, qr[3].u[0], st[6], qs2);
            FMA2(qs3, qr[3].u[1], st[7], qs3);
            ull qsA, qsB, qsC;
            ADD2(qsA, qs0, qs1);
            ADD2(qsB, qs2, qs3);
            ADD2(qsC, qsA, qsB);
            float2 qf = unpack2(qsC);
            float oo = qf.x + qf.y;
            oo += __shfl_xor_sync(0xffffffffu, oo, 1);
            oo += __shfl_xor_sync(0xffffffffu, oo, 2);
            oo += __shfl_xor_sync(0xffffffffu, oo, 4);

            if (p == 0) obase[(size_t)(t0 + tt) * v_stride] = oo;
        }
        __syncthreads();
        buf ^= 1;
    }
}

// ---------------- launch ----------------
extern "C" void kernel_launch(void* const* d_in, const int* in_sizes, int n_in,
                              void* d_out, int out_size)
{
    const float* mixed_qkv = (const float*)d_in[0];
    const float* bvec      = (const float*)d_in[1];
    const float* avec      = (const float*)d_in[2];
    const float* convw     = (const float*)d_in[3];
    const float* dt_bias   = (const float*)d_in[4];
    const float* alog      = (const float*)d_in[5];
    float* out = (float*)d_out;

    prep_kernel<<<NROWS, 256>>>(mixed_qkv, bvec, avec, convw, dt_bias, alog);
    rec_kernel<<<BQ * HV * 2, 512>>>(out);
}

// round 7
// speedup vs baseline: 1.3886x; 1.1640x over previous
#include <cuda_runtime.h>
#include <cuda_bf16.h>
#include <math.h>

#define BQ 2
#define S_LEN 2048
#define HK 16
#define HV 32
#define DK 128
#define DV 128
#define QKV 8192
#define NROWS (BQ * S_LEN)
#define TB 16   // tokens per smem staging batch

typedef unsigned long long ull;

// ---------------- scratch (device globals; no runtime allocation) ----------------
__device__ float g_qn[(size_t)NROWS * HK * DK];    // l2norm(q) * scale
__device__ float g_kn[(size_t)NROWS * HK * DK];    // l2norm(k)
__device__ float g_v [(size_t)NROWS * HV * DV];
__device__ float g_gate[(size_t)NROWS * HV * 2];   // float2 per (row,h): eg, beta

// ---------------- packed f32x2 helpers ----------------
__device__ __forceinline__ ull pack2(float lo, float hi) {
    ull r;
    asm("mov.b64 %0, {%1,%2};" : "=l"(r) : "f"(lo), "f"(hi));
    return r;
}
__device__ __forceinline__ float2 unpack2(ull v) {
    float2 r;
    asm("mov.b64 {%0,%1}, %2;" : "=f"(r.x), "=f"(r.y) : "l"(v));
    return r;
}
#define FMA2(d, a, b, c) asm("fma.rn.f32x2 %0, %1, %2, %3;" : "=l"(d) : "l"(a), "l"(b), "l"(c))
#define MUL2(d, a, b)    asm("mul.rn.f32x2 %0, %1, %2;"     : "=l"(d) : "l"(a), "l"(b))
#define ADD2(d, a, b)    asm("add.rn.f32x2 %0, %1, %2;"     : "=l"(d) : "l"(a), "l"(b))

union F4U { float4 f; ull u[2]; };

// ---------------- kernel 1: conv + silu + l2norm + gating ----------------
__global__ __launch_bounds__(256) void prep_kernel(
    const float* __restrict__ x,      // [NROWS, QKV]
    const float* __restrict__ bvec,   // [NROWS, HV]
    const float* __restrict__ avec,   // [NROWS, HV]
    const float* __restrict__ w,      // [QKV, 4]
    const float* __restrict__ dt_bias,// [HV]
    const float* __restrict__ alog)   // [HV]
{
    const int row = blockIdx.x;
    const int s   = row & (S_LEN - 1);
    const int tid = threadIdx.x;

    __shared__ float ysm[QKV];            // 32 KB

    const float4* w4 = (const float4*)w;  // taps contiguous per channel

    // --- causal depthwise conv (width 4) + SiLU ---
    for (int base = tid * 4; base < QKV; base += 256 * 4) {
        float4 wv0 = __ldg(w4 + base + 0);
        float4 wv1 = __ldg(w4 + base + 1);
        float4 wv2 = __ldg(w4 + base + 2);
        float4 wv3 = __ldg(w4 + base + 3);
        const float* t0 = (const float*)&wv0;
        const float* t1 = (const float*)&wv1;
        const float* t2 = (const float*)&wv2;
        const float* t3 = (const float*)&wv3;
        float4 acc = make_float4(0.f, 0.f, 0.f, 0.f);
#pragma unroll
        for (int j = 0; j < 4; j++) {
            if (s - 3 + j >= 0) {
                const float4 xv = *reinterpret_cast<const float4*>(
                    x + (size_t)(row - 3 + j) * QKV + base);
                acc.x = fmaf(xv.x, t0[j], acc.x);
                acc.y = fmaf(xv.y, t1[j], acc.y);
                acc.z = fmaf(xv.z, t2[j], acc.z);
                acc.w = fmaf(xv.w, t3[j], acc.w);
            }
        }
        acc.x = acc.x / (1.f + __expf(-acc.x));
        acc.y = acc.y / (1.f + __expf(-acc.y));
        acc.z = acc.z / (1.f + __expf(-acc.z));
        acc.w = acc.w / (1.f + __expf(-acc.w));
        *reinterpret_cast<float4*>(ysm + base) = acc;
    }
    __syncthreads();

    const int wi   = tid >> 5;
    const int lane = tid & 31;
    const float qscale = 0.08838834764831845f; // 128^-0.5

    // --- l2 norms for 32 groups (16 q heads + 16 k heads) ---
    for (int gr = wi; gr < 32; gr += 8) {
        const float4 v4 = reinterpret_cast<const float4*>(ysm + gr * 128)[lane];
        float ss = v4.x * v4.x + v4.y * v4.y + v4.z * v4.z + v4.w * v4.w;
#pragma unroll
        for (int o = 16; o > 0; o >>= 1) ss += __shfl_xor_sync(0xffffffffu, ss, o);
        const bool isq = gr < 16;
        const float mul = rsqrtf(ss + 1e-6f) * (isq ? qscale : 1.f);
        float4 ov = make_float4(v4.x * mul, v4.y * mul, v4.z * mul, v4.w * mul);
        if (isq)
            reinterpret_cast<float4*>(g_qn + ((size_t)row * HK + gr) * DK)[lane] = ov;
        else
            reinterpret_cast<float4*>(g_kn + ((size_t)row * HK + (gr - 16)) * DK)[lane] = ov;
    }

    // --- v copy ---
    for (int i = tid * 4; i < HV * DV; i += 256 * 4)
        *reinterpret_cast<float4*>(g_v + (size_t)row * (HV * DV) + i) =
            *reinterpret_cast<const float4*>(ysm + 2 * HK * DK + i);

    // --- gating table (eg, beta) ---
    if (tid < HV) {
        const int h = tid;
        float aa = avec[(size_t)row * HV + h] + dt_bias[h];
        float sp = (aa > 20.f) ? aa : log1pf(expf(aa));
        float g  = -expf(alog[h]) * sp;
        float eg = expf(g);
        float bb = bvec[(size_t)row * HV + h];
        float beta = 1.f / (1.f + expf(-bb));
        *reinterpret_cast<float2*>(g_gate + ((size_t)row * HV + h) * 2) =
            make_float2(eg, beta);
    }
}

// ---------------- kernel 2: gated delta-rule recurrence ----------------
// grid 128 = (b, h, vh). 256 threads = 64 chains x 4 k-slices of 32 dims.
// Thread (c, p): state S[32p..32p+32, col] as 16 packed f32x2.
// Per token: pred on PRE-decay state (eg folded after reduction) -> decay off-path
//   -> 2 shfls for pred INTERLEAVED with 2 shfls of the PREVIOUS token's output
//   reduction (cross-token software pipeline) -> u -> update -> qsum FMAs only
//   (its reduction happens next token). Output store deferred one token.
__global__ __launch_bounds__(256, 1) void rec_kernel(float* __restrict__ out)
{
    const int blk = blockIdx.x;
    const int b   = blk >> 6;
    const int h   = (blk >> 1) & 31;
    const int vh  = blk & 1;
    const int hk  = h >> 1;

    const int tid = threadIdx.x;
    const int c   = tid >> 2;          // chain 0..63
    const int p   = tid & 3;           // k-slice 0..3 (32 dims)

    __shared__ float sk[2][TB][4][36];
    __shared__ float sq[2][TB][4][36];
    __shared__ float sv[2][TB][64];
    __shared__ float2 sg[2][TB];

    ull st[16];
#pragma unroll
    for (int i = 0; i < 16; i++) st[i] = 0ull;

    const float* kbase = g_kn + ((size_t)(b * S_LEN) * HK + hk) * DK;
    const float* qbase = g_qn + ((size_t)(b * S_LEN) * HK + hk) * DK;
    const float* vbase = g_v  + ((size_t)(b * S_LEN) * HV + h) * DV + vh * 64;
    const float* gbase = g_gate + ((size_t)(b * S_LEN) * HV + h) * 2;
    const size_t qk_stride = (size_t)HK * DK;
    const size_t v_stride  = (size_t)HV * DV;

    auto load_batch = [&](int buf, int t0) {
        // k and q: TB tokens x 32 float4 chunks each (512 chunks, 2 rounds each)
#pragma unroll
        for (int rep = 0; rep < 2; rep++) {
            int i  = tid + rep * 256;
            int tt = i >> 5, j = i & 31;
            float4 kv = __ldg((const float4*)(kbase + (size_t)(t0 + tt) * qk_stride) + j);
            *reinterpret_cast<float4*>(&sk[buf][tt][j >> 3][(j & 7) * 4]) = kv;
            float4 qv = __ldg((const float4*)(qbase + (size_t)(t0 + tt) * qk_stride) + j);
            *reinterpret_cast<float4*>(&sq[buf][tt][j >> 3][(j & 7) * 4]) = qv;
        }
        // v: TB x 16 float4 = 256
        {
            int tt = tid >> 4, j = tid & 15;
            *reinterpret_cast<float4*>(&sv[buf][tt][j * 4]) =
                __ldg((const float4*)(vbase + (size_t)(t0 + tt) * v_stride) + j);
        }
        if (tid < TB)
            sg[buf][tid] = *reinterpret_cast<const float2*>(
                gbase + (size_t)(t0 + tid) * (HV * 2));
    };

    load_batch(0, 0);
    __syncthreads();
    int buf = 0;

    float* obase = out + ((size_t)(b * S_LEN) * HV + h) * DV + vh * 64 + c;

    float oo_pend = 0.f;     // previous token's un-reduced qsum partial

#pragma unroll 1
    for (int t0 = 0; t0 < S_LEN; t0 += TB) {
        if (t0 + TB < S_LEN) load_batch(buf ^ 1, t0 + TB);

#pragma unroll 4
        for (int tt = 0; tt < TB; tt++) {
            const int t = t0 + tt;
            const float2 g2 = sg[buf][tt];
            const float eg = g2.x, beta = g2.y;

            // k slice: 32 floats = 8 float4
            F4U kr[8];
            const float* kp = &sk[buf][tt][p][0];
#pragma unroll
            for (int i = 0; i < 8; i++)
                kr[i].f = *reinterpret_cast<const float4*>(kp + i * 4);

            // pred on PRE-decay state, 4 accumulators (depth 4)
            ull pr0 = 0, pr1 = 0, pr2 = 0, pr3 = 0;
#pragma unroll
            for (int i = 0; i < 4; i++) {
                FMA2(pr0, kr[2*i].u[0],   st[4*i+0], pr0);
                FMA2(pr1, kr[2*i].u[1],   st[4*i+1], pr1);
                FMA2(pr2, kr[2*i+1].u[0], st[4*i+2], pr2);
                FMA2(pr3, kr[2*i+1].u[1], st[4*i+3], pr3);
            }

            // decay (off the pred critical path)
            const ull egp = pack2(eg, eg);
#pragma unroll
            for (int i = 0; i < 16; i++) MUL2(st[i], st[i], egp);

            ull prA, prB, prC;
            ADD2(prA, pr0, pr1);
            ADD2(prB, pr2, pr3);
            ADD2(prC, prA, prB);
            float2 pf = unpack2(prC);
            float pred = pf.x + pf.y;

            // interleaved shfl chains: pred (this token) + output (prev token)
            float oo = oo_pend;
            pred += __shfl_xor_sync(0xffffffffu, pred, 1);
            oo   += __shfl_xor_sync(0xffffffffu, oo,   1);
            pred += __shfl_xor_sync(0xffffffffu, pred, 2);
            oo   += __shfl_xor_sync(0xffffffffu, oo,   2);

            // previous token's output store (deferred)
            if (p == 0 && t != 0) obase[(size_t)(t - 1) * v_stride] = oo;

            pred *= eg;
            const float u = beta * (sv[buf][tt][c] - pred);
            const ull up = pack2(u, u);

            // state update (unblocks next token's recurrence)
#pragma unroll
            for (int i = 0; i < 8; i++) {
                FMA2(st[2*i],   kr[i].u[0], up, st[2*i]);
                FMA2(st[2*i+1], kr[i].u[1], up, st[2*i+1]);
            }

            // q slice + qsum FMAs (reduction deferred to next token)
            F4U qr[8];
            const float* qp = &sq[buf][tt][p][0];
#pragma unroll
            for (int i = 0; i < 8; i++)
                qr[i].f = *reinterpret_cast<const float4*>(qp + i * 4);

            ull qs0 = 0, qs1 = 0, qs2 = 0, qs3 = 0;
#pragma unroll
            for (int i = 0; i < 4; i++) {
                FMA2(qs0, qr[2*i].u[0],   st[4*i+0], qs0);
                FMA2(qs1, qr[2*i].u[1],   st[4*i+1], qs1);
                FMA2(qs2, qr[2*i+1].u[0], st[4*i+2], qs2);
                FMA2(qs3, qr[2*i+1].u[1], st[4*i+3], qs3);
            }
            ull qsA, qsB, qsC;
            ADD2(qsA, qs0, qs1);
            ADD2(qsB, qs2, qs3);
            ADD2(qsC, qsA, qsB);
            float2 qf = unpack2(qsC);
            oo_pend = qf.x + qf.y;
        }
        __syncthreads();
        buf ^= 1;
    }

    // drain: reduce and store the final token's output
    {
        float oo = oo_pend;
        oo += __shfl_xor_sync(0xffffffffu, oo, 1);
        oo += __shfl_xor_sync(0xffffffffu, oo, 2);
        if (p == 0) obase[(size_t)(S_LEN - 1) * v_stride] = oo;
    }
}

// ---------------- launch ----------------
extern "C" void kernel_launch(void* const* d_in, const int* in_sizes, int n_in,
                              void* d_out, int out_size)
{
    const float* mixed_qkv = (const float*)d_in[0];
    const float* bvec      = (const float*)d_in[1];
    const float* avec      = (const float*)d_in[2];
    const float* convw     = (const float*)d_in[3];
    const float* dt_bias   = (const float*)d_in[4];
    const float* alog      = (const float*)d_in[5];
    float* out = (float*)d_out;

    prep_kernel<<<NROWS, 256>>>(mixed_qkv, bvec, avec, convw, dt_bias, alog);
    rec_kernel<<<BQ * HV * 2, 256>>>(out);
}

// round 8
// speedup vs baseline: 1.6110x; 1.1602x over previous
#include <cuda_runtime.h>
#include <cuda_bf16.h>
#include <math.h>

#define BQ 2
#define S_LEN 2048
#define HK 16
#define HV 32
#define DK 128
#define DV 128
#define QKV 8192
#define NROWS (BQ * S_LEN)
#define TB 16   // tokens per smem staging batch

typedef unsigned long long ull;

// ---------------- scratch (device globals; no runtime allocation) ----------------
__device__ float g_qn[(size_t)NROWS * HK * DK];    // l2norm(q) * scale
__device__ float g_kn[(size_t)NROWS * HK * DK];    // l2norm(k)
__device__ float g_v [(size_t)NROWS * HV * DV];
__device__ float g_gate[(size_t)NROWS * HV * 2];   // float2 per (row,h): eg, beta

// ---------------- packed f32x2 helpers ----------------
__device__ __forceinline__ ull pack2(float lo, float hi) {
    ull r;
    asm("mov.b64 %0, {%1,%2};" : "=l"(r) : "f"(lo), "f"(hi));
    return r;
}
__device__ __forceinline__ float2 unpack2(ull v) {
    float2 r;
    asm("mov.b64 {%0,%1}, %2;" : "=f"(r.x), "=f"(r.y) : "l"(v));
    return r;
}
#define FMA2(d, a, b, c) asm("fma.rn.f32x2 %0, %1, %2, %3;" : "=l"(d) : "l"(a), "l"(b), "l"(c))
#define MUL2(d, a, b)    asm("mul.rn.f32x2 %0, %1, %2;"     : "=l"(d) : "l"(a), "l"(b))
#define ADD2(d, a, b)    asm("add.rn.f32x2 %0, %1, %2;"     : "=l"(d) : "l"(a), "l"(b))

union F4U { float4 f; ull u[2]; };

// ---------------- kernel 1: conv + silu + l2norm + gating ----------------
__global__ __launch_bounds__(256) void prep_kernel(
    const float* __restrict__ x,      // [NROWS, QKV]
    const float* __restrict__ bvec,   // [NROWS, HV]
    const float* __restrict__ avec,   // [NROWS, HV]
    const float* __restrict__ w,      // [QKV, 4]
    const float* __restrict__ dt_bias,// [HV]
    const float* __restrict__ alog)   // [HV]
{
    const int row = blockIdx.x;
    const int s   = row & (S_LEN - 1);
    const int tid = threadIdx.x;

    __shared__ float ysm[QKV];            // 32 KB

    const float4* w4 = (const float4*)w;  // taps contiguous per channel

    // --- causal depthwise conv (width 4) + SiLU ---
    for (int base = tid * 4; base < QKV; base += 256 * 4) {
        float4 wv0 = __ldg(w4 + base + 0);
        float4 wv1 = __ldg(w4 + base + 1);
        float4 wv2 = __ldg(w4 + base + 2);
        float4 wv3 = __ldg(w4 + base + 3);
        const float* t0 = (const float*)&wv0;
        const float* t1 = (const float*)&wv1;
        const float* t2 = (const float*)&wv2;
        const float* t3 = (const float*)&wv3;
        float4 acc = make_float4(0.f, 0.f, 0.f, 0.f);
#pragma unroll
        for (int j = 0; j < 4; j++) {
            if (s - 3 + j >= 0) {
                const float4 xv = *reinterpret_cast<const float4*>(
                    x + (size_t)(row - 3 + j) * QKV + base);
                acc.x = fmaf(xv.x, t0[j], acc.x);
                acc.y = fmaf(xv.y, t1[j], acc.y);
                acc.z = fmaf(xv.z, t2[j], acc.z);
                acc.w = fmaf(xv.w, t3[j], acc.w);
            }
        }
        acc.x = acc.x / (1.f + __expf(-acc.x));
        acc.y = acc.y / (1.f + __expf(-acc.y));
        acc.z = acc.z / (1.f + __expf(-acc.z));
        acc.w = acc.w / (1.f + __expf(-acc.w));
        *reinterpret_cast<float4*>(ysm + base) = acc;
    }
    __syncthreads();

    const int wi   = tid >> 5;
    const int lane = tid & 31;
    const float qscale = 0.08838834764831845f; // 128^-0.5

    // --- l2 norms for 32 groups (16 q heads + 16 k heads) ---
    for (int gr = wi; gr < 32; gr += 8) {
        const float4 v4 = reinterpret_cast<const float4*>(ysm + gr * 128)[lane];
        float ss = v4.x * v4.x + v4.y * v4.y + v4.z * v4.z + v4.w * v4.w;
#pragma unroll
        for (int o = 16; o > 0; o >>= 1) ss += __shfl_xor_sync(0xffffffffu, ss, o);
        const bool isq = gr < 16;
        const float mul = rsqrtf(ss + 1e-6f) * (isq ? qscale : 1.f);
        float4 ov = make_float4(v4.x * mul, v4.y * mul, v4.z * mul, v4.w * mul);
        if (isq)
            reinterpret_cast<float4*>(g_qn + ((size_t)row * HK + gr) * DK)[lane] = ov;
        else
            reinterpret_cast<float4*>(g_kn + ((size_t)row * HK + (gr - 16)) * DK)[lane] = ov;
    }

    // --- v copy ---
    for (int i = tid * 4; i < HV * DV; i += 256 * 4)
        *reinterpret_cast<float4*>(g_v + (size_t)row * (HV * DV) + i) =
            *reinterpret_cast<const float4*>(ysm + 2 * HK * DK + i);

    // --- gating table (eg, beta) ---
    if (tid < HV) {
        const int h = tid;
        float aa = avec[(size_t)row * HV + h] + dt_bias[h];
        float sp = (aa > 20.f) ? aa : log1pf(expf(aa));
        float g  = -expf(alog[h]) * sp;
        float eg = expf(g);
        float bb = bvec[(size_t)row * HV + h];
        float beta = 1.f / (1.f + expf(-bb));
        *reinterpret_cast<float2*>(g_gate + ((size_t)row * HV + h) * 2) =
            make_float2(eg, beta);
    }
}

// ---------------- kernel 2: gated delta-rule recurrence ----------------
// grid 128 = (b, h, vh). 256 threads = 32 column-PAIRS x 8 k-slices of 16 dims.
// Thread (c2, p): state S[16p..16p+16, {2c2, 2c2+1}] as 2x8 packed f32x2.
// Each k/q slice load feeds TWO columns (halves LDS vs 1-col layout).
// Reductions: owner-split butterfly over the 8 p-lanes — low 4 lanes own value0,
// high own value1: 1 fold shfl + 2 tree shfls (+1 broadcast for preds only).
// Output reduction deferred one token (interleaved with next pred reduction);
// lanes p==0 / p==4 store col0 / col1 scalars.
__global__ __launch_bounds__(256, 1) void rec_kernel(float* __restrict__ out)
{
    const int blk = blockIdx.x;
    const int b   = blk >> 6;
    const int h   = (blk >> 1) & 31;
    const int vh  = blk & 1;
    const int hk  = h >> 1;

    const int tid = threadIdx.x;
    const int c2  = tid >> 3;          // column pair 0..31
    const int p   = tid & 7;           // k-slice 0..7 (16 dims)
    const bool lowp = (p < 4);

    __shared__ float sk[2][TB][8][20];   // 8 groups x 16 floats pad 20: conflict-free
    __shared__ float sq[2][TB][8][20];
    __shared__ float sv[2][TB][64];
    __shared__ float2 sg[2][TB];

    ull s0[8], s1[8];
#pragma unroll
    for (int i = 0; i < 8; i++) { s0[i] = 0ull; s1[i] = 0ull; }

    const float* kbase = g_kn + ((size_t)(b * S_LEN) * HK + hk) * DK;
    const float* qbase = g_qn + ((size_t)(b * S_LEN) * HK + hk) * DK;
    const float* vbase = g_v  + ((size_t)(b * S_LEN) * HV + h) * DV + vh * 64;
    const float* gbase = g_gate + ((size_t)(b * S_LEN) * HV + h) * 2;
    const size_t qk_stride = (size_t)HK * DK;
    const size_t v_stride  = (size_t)HV * DV;

    auto load_batch = [&](int buf, int t0) {
        // k and q: TB tokens x 32 float4 chunks each (512 chunks, 2 rounds each)
#pragma unroll
        for (int rep = 0; rep < 2; rep++) {
            int i  = tid + rep * 256;
            int tt = i >> 5, j = i & 31;
            float4 kv = __ldg((const float4*)(kbase + (size_t)(t0 + tt) * qk_stride) + j);
            *reinterpret_cast<float4*>(&sk[buf][tt][j >> 2][(j & 3) * 4]) = kv;
            float4 qv = __ldg((const float4*)(qbase + (size_t)(t0 + tt) * qk_stride) + j);
            *reinterpret_cast<float4*>(&sq[buf][tt][j >> 2][(j & 3) * 4]) = qv;
        }
        // v: TB x 16 float4 = 256
        {
            int tt = tid >> 4, j = tid & 15;
            *reinterpret_cast<float4*>(&sv[buf][tt][j * 4]) =
                __ldg((const float4*)(vbase + (size_t)(t0 + tt) * v_stride) + j);
        }
        if (tid < TB)
            sg[buf][tid] = *reinterpret_cast<const float2*>(
                gbase + (size_t)(t0 + tid) * (HV * 2));
    };

    load_batch(0, 0);
    __syncthreads();
    int buf = 0;

    float* obase = out + ((size_t)(b * S_LEN) * HV + h) * DV + vh * 64 + c2 * 2;
    const int osel = lowp ? 0 : 1;     // which column this lane's owner-value maps to

    float oo_m = 0.f, oo_o = 0.f;      // prev token's output partials (owner-split)

#pragma unroll 1
    for (int t0 = 0; t0 < S_LEN; t0 += TB) {
        if (t0 + TB < S_LEN) load_batch(buf ^ 1, t0 + TB);

#pragma unroll 4
        for (int tt = 0; tt < TB; tt++) {
            const int t = t0 + tt;
            const float2 g2 = sg[buf][tt];
            const float eg = g2.x, beta = g2.y;

            // k slice: 16 floats = 4 float4 (feeds both columns)
            F4U kr[4];
            const float* kp = &sk[buf][tt][p][0];
#pragma unroll
            for (int i = 0; i < 4; i++)
                kr[i].f = *reinterpret_cast<const float4*>(kp + i * 4);

            // pred partials on PRE-decay state (2 accums per column, depth 4)
            ull pa0 = 0, pa1 = 0, pb0 = 0, pb1 = 0;
#pragma unroll
            for (int i = 0; i < 4; i++) {
                FMA2(pa0, kr[i].u[0], s0[2*i],   pa0);
                FMA2(pa1, kr[i].u[1], s0[2*i+1], pa1);
                FMA2(pb0, kr[i].u[0], s1[2*i],   pb0);
                FMA2(pb1, kr[i].u[1], s1[2*i+1], pb1);
            }

            // decay both columns (off the pred critical path)
            const ull egp = pack2(eg, eg);
#pragma unroll
            for (int i = 0; i < 8; i++) { MUL2(s0[i], s0[i], egp); MUL2(s1[i], s1[i], egp); }

            ull pA, pB;
            ADD2(pA, pa0, pa1);
            ADD2(pB, pb0, pb1);
            float2 fA = unpack2(pA), fB = unpack2(pB);
            const float p0 = fA.x + fA.y;    // col0 partial
            const float p1 = fB.x + fB.y;    // col1 partial

            // owner-split butterfly: low lanes own p0, high own p1;
            // interleave prev token's output reduction (owners already split)
            float mine  = lowp ? p0 : p1;
            float other = lowp ? p1 : p0;
            mine += __shfl_xor_sync(0xffffffffu, other, 4);
            oo_m += __shfl_xor_sync(0xffffffffu, oo_o,  4);
            mine += __shfl_xor_sync(0xffffffffu, mine, 1);
            oo_m += __shfl_xor_sync(0xffffffffu, oo_m,  1);
            mine += __shfl_xor_sync(0xffffffffu, mine, 2);
            oo_m += __shfl_xor_sync(0xffffffffu, oo_m,  2);
            const float both = __shfl_xor_sync(0xffffffffu, mine, 4);

            // prev token's output store (lanes p==0 and p==4, one column each)
            if (t != 0 && (p & 3) == 0)
                obase[(size_t)(t - 1) * v_stride + osel] = oo_m;

            const float pred0 = lowp ? mine : both;
            const float pred1 = lowp ? both : mine;
            const float2 v2 = *reinterpret_cast<const float2*>(&sv[buf][tt][c2 * 2]);
            const float u0 = beta * (v2.x - eg * pred0);
            const float u1 = beta * (v2.y - eg * pred1);
            const ull up0 = pack2(u0, u0), up1 = pack2(u1, u1);

            // state update (unblocks next token's recurrence)
#pragma unroll
            for (int i = 0; i < 4; i++) {
                FMA2(s0[2*i],   kr[i].u[0], up0, s0[2*i]);
                FMA2(s0[2*i+1], kr[i].u[1], up0, s0[2*i+1]);
                FMA2(s1[2*i],   kr[i].u[0], up1, s1[2*i]);
                FMA2(s1[2*i+1], kr[i].u[1], up1, s1[2*i+1]);
            }

            // q slice + qsum partials (reduction deferred to next token)
            F4U qr[4];
            const float* qp = &sq[buf][tt][p][0];
#pragma unroll
            for (int i = 0; i < 4; i++)
                qr[i].f = *reinterpret_cast<const float4*>(qp + i * 4);

            ull qa0 = 0, qa1 = 0, qb0 = 0, qb1 = 0;
#pragma unroll
            for (int i = 0; i < 4; i++) {
                FMA2(qa0, qr[i].u[0], s0[2*i],   qa0);
                FMA2(qa1, qr[i].u[1], s0[2*i+1], qa1);
                FMA2(qb0, qr[i].u[0], s1[2*i],   qb0);
                FMA2(qb1, qr[i].u[1], s1[2*i+1], qb1);
            }
            ull qA, qB;
            ADD2(qA, qa0, qa1);
            ADD2(qB, qb0, qb1);
            float2 gA = unpack2(qA), gB = unpack2(qB);
            const float q0 = gA.x + gA.y;
            const float q1 = gB.x + gB.y;
            oo_m = lowp ? q0 : q1;
            oo_o = lowp ? q1 : q0;
        }
        __syncthreads();
        buf ^= 1;
    }

    // drain: reduce and store the final token's output
    {
        oo_m += __shfl_xor_sync(0xffffffffu, oo_o, 4);
        oo_m += __shfl_xor_sync(0xffffffffu, oo_m, 1);
        oo_m += __shfl_xor_sync(0xffffffffu, oo_m, 2);
        if ((p & 3) == 0)
            obase[(size_t)(S_LEN - 1) * v_stride + osel] = oo_m;
    }
}

// ---------------- launch ----------------
extern "C" void kernel_launch(void* const* d_in, const int* in_sizes, int n_in,
                              void* d_out, int out_size)
{
    const float* mixed_qkv = (const float*)d_in[0];
    const float* bvec      = (const float*)d_in[1];
    const float* avec      = (const float*)d_in[2];
    const float* convw     = (const float*)d_in[3];
    const float* dt_bias   = (const float*)d_in[4];
    const float* alog      = (const float*)d_in[5];
    float* out = (float*)d_out;

    prep_kernel<<<NROWS, 256>>>(mixed_qkv, bvec, avec, convw, dt_bias, alog);
    rec_kernel<<<BQ * HV * 2, 256>>>(out);
}

// round 9
// speedup vs baseline: 1.7054x; 1.0586x over previous
#include <cuda_runtime.h>
#include <cuda_bf16.h>
#include <math.h>

#define BQ 2
#define S_LEN 2048
#define HK 16
#define HV 32
#define DK 128
#define DV 128
#define QKV 8192
#define NROWS (BQ * S_LEN)
#define TB 16   // tokens per smem staging batch (rec)
#define CT 16   // tokens per conv tile (prep)

typedef unsigned long long ull;

// ---------------- scratch (device globals; no runtime allocation) ----------------
__device__ float g_qn[(size_t)NROWS * HK * DK];    // l2norm(q) * scale
__device__ float g_kn[(size_t)NROWS * HK * DK];    // l2norm(k)
__device__ float g_v [(size_t)NROWS * HV * DV];
__device__ float g_gate[(size_t)NROWS * HV * 2];   // float2 per (row,h): eg, beta

// ---------------- packed f32x2 helpers ----------------
__device__ __forceinline__ ull pack2(float lo, float hi) {
    ull r;
    asm("mov.b64 %0, {%1,%2};" : "=l"(r) : "f"(lo), "f"(hi));
    return r;
}
__device__ __forceinline__ float2 unpack2(ull v) {
    float2 r;
    asm("mov.b64 {%0,%1}, %2;" : "=f"(r.x), "=f"(r.y) : "l"(v));
    return r;
}
#define FMA2(d, a, b, c) asm("fma.rn.f32x2 %0, %1, %2, %3;" : "=l"(d) : "l"(a), "l"(b), "l"(c))
#define MUL2(d, a, b)    asm("mul.rn.f32x2 %0, %1, %2;"     : "=l"(d) : "l"(a), "l"(b))
#define ADD2(d, a, b)    asm("add.rn.f32x2 %0, %1, %2;"     : "=l"(d) : "l"(a), "l"(b))

union F4U { float4 f; ull u[2]; };

// ---------------- cp.async helpers ----------------
__device__ __forceinline__ void cpa16(void* smem, const void* gmem) {
    unsigned s = (unsigned)__cvta_generic_to_shared(smem);
    asm volatile("cp.async.cg.shared.global [%0], [%1], 16;" :: "r"(s), "l"(gmem));
}
__device__ __forceinline__ void cpa8(void* smem, const void* gmem) {
    unsigned s = (unsigned)__cvta_generic_to_shared(smem);
    asm volatile("cp.async.ca.shared.global [%0], [%1], 8;" :: "r"(s), "l"(gmem));
}
__device__ __forceinline__ void cpa_commit() {
    asm volatile("cp.async.commit_group;" ::: "memory");
}
__device__ __forceinline__ void cpa_wait0() {
    asm volatile("cp.async.wait_group 0;" ::: "memory");
}

// ---------------- kernel 1: tiled conv + silu + l2norm ----------------
// grid = 32 strips x 128 chunks x 2 batches = 8192 blocks, 256 threads.
// Each block: tile of CT=16 tokens x 256 channels. x read once (+3-row halo).
// Strips align with heads: strip<8 -> q heads 2s,2s+1; 8..15 -> k; 16..31 -> v.
__global__ __launch_bounds__(256) void prep_kernel(
    const float* __restrict__ x,      // [NROWS, QKV]
    const float* __restrict__ w)      // [QKV, 4]
{
    const int bx    = blockIdx.x;
    const int strip = bx & 31;
    const int chunk = (bx >> 5) & 127;
    const int b     = bx >> 12;
    const int T0    = chunk * CT;
    const int ch0   = strip * 256;
    const int tid   = threadIdx.x;

    __shared__ float xs[CT + 3][256];
    __shared__ float ys[CT][256];

    // --- load CT+3 token rows of this strip (halo = zero history) ---
    for (int i = tid; i < (CT + 3) * 64; i += 256) {
        int r = i >> 6, j = i & 63;
        int tok = T0 - 3 + r;
        float4 val = make_float4(0.f, 0.f, 0.f, 0.f);
        if (tok >= 0)
            val = *reinterpret_cast<const float4*>(
                x + (size_t)(b * S_LEN + tok) * QKV + ch0 + j * 4);
        *reinterpret_cast<float4*>(&xs[r][j * 4]) = val;
    }
    __syncthreads();

    // --- conv(width 4) + SiLU : 4 outputs (float4) per thread ---
    const float4* w4 = (const float4*)w;
#pragma unroll
    for (int rep = 0; rep < 4; rep++) {
        int i = tid + rep * 256;            // 0..1023
        int t = i >> 6, j = i & 63;
        int ch = ch0 + j * 4;
        float4 wv0 = __ldg(w4 + ch + 0);
        float4 wv1 = __ldg(w4 + ch + 1);
        float4 wv2 = __ldg(w4 + ch + 2);
        float4 wv3 = __ldg(w4 + ch + 3);
        const float* t0 = (const float*)&wv0;
        const float* t1 = (const float*)&wv1;
        const float* t2 = (const float*)&wv2;
        const float* t3 = (const float*)&wv3;
        float4 acc = make_float4(0.f, 0.f, 0.f, 0.f);
#pragma unroll
        for (int jj = 0; jj < 4; jj++) {
            const float4 xv = *reinterpret_cast<const float4*>(&xs[t + jj][j * 4]);
            acc.x = fmaf(xv.x, t0[jj], acc.x);
            acc.y = fmaf(xv.y, t1[jj], acc.y);
            acc.z = fmaf(xv.z, t2[jj], acc.z);
            acc.w = fmaf(xv.w, t3[jj], acc.w);
        }
        acc.x = acc.x / (1.f + __expf(-acc.x));
        acc.y = acc.y / (1.f + __expf(-acc.y));
        acc.z = acc.z / (1.f + __expf(-acc.z));
        acc.w = acc.w / (1.f + __expf(-acc.w));
        *reinterpret_cast<float4*>(&ys[t][j * 4]) = acc;
    }
    __syncthreads();

    // --- per-head l2norm (q/k strips) or copy (v strips) ---
    // thread = (tok, seg): tok=tid>>4 (16 tokens), seg=tid&15 (16 chans each).
    // head within strip = seg>>3; 8 segs/head reduce via 3 shfls (same warp).
    const int tok = tid >> 4;
    const int seg = tid & 15;
    const int row = b * S_LEN + T0 + tok;
    const float* yp = &ys[tok][seg * 16];
    const float qscale = 0.08838834764831845f; // 128^-0.5

    if (strip < 16) {
        float ss = 0.f;
#pragma unroll
        for (int i = 0; i < 4; i++) {
            float4 v = *reinterpret_cast<const float4*>(yp + i * 4);
            ss += v.x * v.x + v.y * v.y + v.z * v.z + v.w * v.w;
        }
        ss += __shfl_xor_sync(0xffffffffu, ss, 1);
        ss += __shfl_xor_sync(0xffffffffu, ss, 2);
        ss += __shfl_xor_sync(0xffffffffu, ss, 4);
        const bool isq = strip < 8;
        const int head = (isq ? strip * 2 : (strip - 8) * 2) + (seg >> 3);
        const float mul = rsqrtf(ss + 1e-6f) * (isq ? qscale : 1.f);
        float* dst = (isq ? g_qn : g_kn)
                   + ((size_t)row * HK + head) * DK + (seg & 7) * 16;
#pragma unroll
        for (int i = 0; i < 4; i++) {
            float4 v = *reinterpret_cast<const float4*>(yp + i * 4);
            v.x *= mul; v.y *= mul; v.z *= mul; v.w *= mul;
            *reinterpret_cast<float4*>(dst + i * 4) = v;
        }
    } else {
        const int head = (strip - 16) * 2 + (seg >> 3);
        float* dst = g_v + ((size_t)row * HV + head) * DV + (seg & 7) * 16;
#pragma unroll
        for (int i = 0; i < 4; i++)
            *reinterpret_cast<float4*>(dst + i * 4) =
                *reinterpret_cast<const float4*>(yp + i * 4);
    }
}

// ---------------- kernel 1b: gating ----------------
__global__ __launch_bounds__(256) void gate_kernel(
    const float* __restrict__ bvec,   // [NROWS, HV]
    const float* __restrict__ avec,   // [NROWS, HV]
    const float* __restrict__ dt_bias,// [HV]
    const float* __restrict__ alog)   // [HV]
{
    const int idx = blockIdx.x * 256 + threadIdx.x;   // < NROWS*HV = 131072
    const int h = idx & 31;
    float aa = avec[idx] + __ldg(dt_bias + h);
    float sp = (aa > 20.f) ? aa : log1pf(expf(aa));
    float g  = -expf(__ldg(alog + h)) * sp;
    float eg = expf(g);
    float bb = bvec[idx];
    float beta = 1.f / (1.f + expf(-bb));
    *reinterpret_cast<float2*>(g_gate + (size_t)idx * 2) = make_float2(eg, beta);
}

// ---------------- kernel 2: gated delta-rule recurrence ----------------
// grid 128 = (b, h, vh). 256 threads = 32 column-PAIRS x 8 k-slices of 16 dims.
// Thread (c2, p): state S[16p..16p+16, {2c2, 2c2+1}] as 2x8 packed f32x2.
// cp.async staging (1 group in flight, waited before the batch barrier).
// kr double-buffered in registers: token t+1's k slice LDS issues before token
// t's reduction -> LDS off the recurrence critical chain.
// Reductions: owner-split butterfly (low 4 lanes own col0, high own col1);
// output reduction deferred one token and interleaved with the next pred.
__global__ __launch_bounds__(256, 1) void rec_kernel(float* __restrict__ out)
{
    const int blk = blockIdx.x;
    const int b   = blk >> 6;
    const int h   = (blk >> 1) & 31;
    const int vh  = blk & 1;
    const int hk  = h >> 1;

    const int tid = threadIdx.x;
    const int c2  = tid >> 3;          // column pair 0..31
    const int p   = tid & 7;           // k-slice 0..7 (16 dims)
    const bool lowp = (p < 4);

    __shared__ float sk[2][TB][8][20];   // 8 groups x 16 floats pad 20: conflict-free
    __shared__ float sq[2][TB][8][20];
    __shared__ float sv[2][TB][64];
    __shared__ float2 sg[2][TB];

    ull s0[8], s1[8];
#pragma unroll
    for (int i = 0; i < 8; i++) { s0[i] = 0ull; s1[i] = 0ull; }

    const float* kbase = g_kn + ((size_t)(b * S_LEN) * HK + hk) * DK;
    const float* qbase = g_qn + ((size_t)(b * S_LEN) * HK + hk) * DK;
    const float* vbase = g_v  + ((size_t)(b * S_LEN) * HV + h) * DV + vh * 64;
    const float* gbase = g_gate + ((size_t)(b * S_LEN) * HV + h) * 2;
    const size_t qk_stride = (size_t)HK * DK;
    const size_t v_stride  = (size_t)HV * DV;

    auto load_batch = [&](int buf, int t0) {
        // k and q: TB tokens x 32 float4 chunks each (512 each, 2 rounds)
#pragma unroll
        for (int rep = 0; rep < 2; rep++) {
            int i  = tid + rep * 256;
            int tt = i >> 5, j = i & 31;
            cpa16(&sk[buf][tt][j >> 2][(j & 3) * 4],
                  kbase + (size_t)(t0 + tt) * qk_stride + j * 4);
            cpa16(&sq[buf][tt][j >> 2][(j & 3) * 4],
                  qbase + (size_t)(t0 + tt) * qk_stride + j * 4);
        }
        // v: TB x 16 float4 = 256
        {
            int tt = tid >> 4, j = tid & 15;
            cpa16(&sv[buf][tt][j * 4],
                  vbase + (size_t)(t0 + tt) * v_stride + j * 4);
        }
        if (tid < TB)
            cpa8(&sg[buf][tid], gbase + (size_t)(t0 + tid) * (HV * 2));
        cpa_commit();
    };

    load_batch(0, 0);
    cpa_wait0();
    __syncthreads();
    int buf = 0;

    float* obase = out + ((size_t)(b * S_LEN) * HV + h) * DV + vh * 64 + c2 * 2;
    const int osel = lowp ? 0 : 1;

    float oo_m = 0.f, oo_o = 0.f;      // prev token's output partials (owner-split)

    F4U krA[4], krB[4];

#define LOADK(dst, bufv, ttv) do {                                            \
    const float* _kp = &sk[bufv][ttv][p][0];                                  \
    dst[0].f = *reinterpret_cast<const float4*>(_kp + 0);                     \
    dst[1].f = *reinterpret_cast<const float4*>(_kp + 4);                     \
    dst[2].f = *reinterpret_cast<const float4*>(_kp + 8);                     \
    dst[3].f = *reinterpret_cast<const float4*>(_kp + 12);                    \
} while (0)

#define BODY(kr, TT, T) do {                                                  \
    const float2 g2 = sg[buf][TT];                                            \
    const float eg = g2.x, beta = g2.y;                                       \
    ull pa0 = 0, pa1 = 0, pb0 = 0, pb1 = 0;                                   \
    _Pragma("unroll")                                                         \
    for (int i = 0; i < 4; i++) {                                             \
        FMA2(pa0, kr[i].u[0], s0[2*i],   pa0);                                \
        FMA2(pa1, kr[i].u[1], s0[2*i+1], pa1);                                \
        FMA2(pb0, kr[i].u[0], s1[2*i],   pb0);                                \
        FMA2(pb1, kr[i].u[1], s1[2*i+1], pb1);                                \
    }                                                                         \
    const ull egp = pack2(eg, eg);                                            \
    _Pragma("unroll")                                                         \
    for (int i = 0; i < 8; i++) { MUL2(s0[i], s0[i], egp); MUL2(s1[i], s1[i], egp); } \
    ull pA, pB;                                                               \
    ADD2(pA, pa0, pa1);                                                       \
    ADD2(pB, pb0, pb1);                                                       \
    float2 fA = unpack2(pA), fB = unpack2(pB);                                \
    const float p0 = fA.x + fA.y;                                             \
    const float p1 = fB.x + fB.y;                                             \
    float mine  = lowp ? p0 : p1;                                             \
    float other = lowp ? p1 : p0;                                             \
    mine += __shfl_xor_sync(0xffffffffu, other, 4);                           \
    oo_m += __shfl_xor_sync(0xffffffffu, oo_o,  4);                           \
    mine += __shfl_xor_sync(0xffffffffu, mine, 1);                            \
    oo_m += __shfl_xor_sync(0xffffffffu, oo_m,  1);                           \
    mine += __shfl_xor_sync(0xffffffffu, mine, 2);                            \
    oo_m += __shfl_xor_sync(0xffffffffu, oo_m,  2);                           \
    const float both = __shfl_xor_sync(0xffffffffu, mine, 4);                 \
    if ((T) != 0 && (p & 3) == 0)                                             \
        obase[(size_t)((T) - 1) * v_stride + osel] = oo_m;                    \
    const float pred0 = lowp ? mine : both;                                   \
    const float pred1 = lowp ? both : mine;                                   \
    const float2 v2 = *reinterpret_cast<const float2*>(&sv[buf][TT][c2 * 2]); \
    const float u0 = beta * (v2.x - eg * pred0);                              \
    const float u1 = beta * (v2.y - eg * pred1);                              \
    const ull up0 = pack2(u0, u0), up1 = pack2(u1, u1);                       \
    _Pragma("unroll")                                                         \
    for (int i = 0; i < 4; i++) {                                             \
        FMA2(s0[2*i],   kr[i].u[0], up0, s0[2*i]);                            \
        FMA2(s0[2*i+1], kr[i].u[1], up0, s0[2*i+1]);                          \
        FMA2(s1[2*i],   kr[i].u[0], up1, s1[2*i]);                            \
        FMA2(s1[2*i+1], kr[i].u[1], up1, s1[2*i+1]);                          \
    }                                                                         \
    F4U qr[4];                                                                \
    const float* qp = &sq[buf][TT][p][0];                                     \
    _Pragma("unroll")                                                         \
    for (int i = 0; i < 4; i++)                                               \
        qr[i].f = *reinterpret_cast<const float4*>(qp + i * 4);               \
    ull qa0 = 0, qa1 = 0, qb0 = 0, qb1 = 0;                                   \
    _Pragma("unroll")                                                         \
    for (int i = 0; i < 4; i++) {                                             \
        FMA2(qa0, qr[i].u[0], s0[2*i],   qa0);                                \
        FMA2(qa1, qr[i].u[1], s0[2*i+1], qa1);                                \
        FMA2(qb0, qr[i].u[0], s1[2*i],   qb0);                                \
        FMA2(qb1, qr[i].u[1], s1[2*i+1], qb1);                                \
    }                                                                         \
    ull qA, qB;                                                               \
    ADD2(qA, qa0, qa1);                                                       \
    ADD2(qB, qb0, qb1);                                                       \
    float2 gA = unpack2(qA), gB = unpack2(qB);                                \
    const float q0 = gA.x + gA.y;                                             \
    const float q1 = gB.x + gB.y;                                             \
    oo_m = lowp ? q0 : q1;                                                    \
    oo_o = lowp ? q1 : q0;                                                    \
} while (0)

#pragma unroll 1
    for (int t0 = 0; t0 < S_LEN; t0 += TB) {
        if (t0 + TB < S_LEN) load_batch(buf ^ 1, t0 + TB);

        LOADK(krA, buf, 0);
#pragma unroll 2
        for (int tt = 0; tt < TB; tt += 2) {
            LOADK(krB, buf, tt + 1);
            BODY(krA, tt, t0 + tt);
            {
                int tn = tt + 2; if (tn > TB - 1) tn = TB - 1;
                LOADK(krA, buf, tn);
            }
            BODY(krB, tt + 1, t0 + tt + 1);
        }

        cpa_wait0();
        __syncthreads();
        buf ^= 1;
    }

    // drain: reduce and store the final token's output
    {
        oo_m += __shfl_xor_sync(0xffffffffu, oo_o, 4);
        oo_m += __shfl_xor_sync(0xffffffffu, oo_m, 1);
        oo_m += __shfl_xor_sync(0xffffffffu, oo_m, 2);
        if ((p & 3) == 0)
            obase[(size_t)(S_LEN - 1) * v_stride + osel] = oo_m;
    }
#undef LOADK
#undef BODY
}

// ---------------- launch ----------------
extern "C" void kernel_launch(void* const* d_in, const int* in_sizes, int n_in,
                              void* d_out, int out_size)
{
    const float* mixed_qkv = (const float*)d_in[0];
    const float* bvec      = (const float*)d_in[1];
    const float* avec      = (const float*)d_in[2];
    const float* convw     = (const float*)d_in[3];
    const float* dt_bias   = (const float*)d_in[4];
    const float* alog      = (const float*)d_in[5];
    float* out = (float*)d_out;

    prep_kernel<<<32 * (S_LEN / CT) * BQ, 256>>>(mixed_qkv, convw);
    gate_kernel<<<NROWS * HV / 256, 256>>>(bvec, avec, dt_bias, alog);
    rec_kernel<<<BQ * HV * 2, 256>>>(out);
}

// round 10
// speedup vs baseline: 1.8101x; 1.0614x over previous
#include <cuda_runtime.h>
#include <cuda_bf16.h>
#include <math.h>

#define BQ 2
#define S_LEN 2048
#define HK 16
#define HV 32
#define DK 128
#define DV 128
#define QKV 8192
#define NROWS (BQ * S_LEN)
#define TB 16   // tokens per smem staging batch (rec)

typedef unsigned long long ull;

// ---------------- scratch (device globals; no runtime allocation) ----------------
__device__ float g_qn[(size_t)NROWS * HK * DK];    // l2norm(q) * scale
__device__ float g_kn[(size_t)NROWS * HK * DK];    // l2norm(k)
__device__ float g_v [(size_t)NROWS * HV * DV];
__device__ float g_gate[(size_t)NROWS * HV * 2];   // float2 per (row,h): eg, beta

// ---------------- packed f32x2 helpers ----------------
__device__ __forceinline__ ull pack2(float lo, float hi) {
    ull r;
    asm("mov.b64 %0, {%1,%2};" : "=l"(r) : "f"(lo), "f"(hi));
    return r;
}
__device__ __forceinline__ float2 unpack2(ull v) {
    float2 r;
    asm("mov.b64 {%0,%1}, %2;" : "=f"(r.x), "=f"(r.y) : "l"(v));
    return r;
}
#define FMA2(d, a, b, c) asm("fma.rn.f32x2 %0, %1, %2, %3;" : "=l"(d) : "l"(a), "l"(b), "l"(c))
#define MUL2(d, a, b)    asm("mul.rn.f32x2 %0, %1, %2;"     : "=l"(d) : "l"(a), "l"(b))
#define ADD2(d, a, b)    asm("add.rn.f32x2 %0, %1, %2;"     : "=l"(d) : "l"(a), "l"(b))

union F4U { float4 f; ull u[2]; };

// ---------------- cp.async helpers ----------------
__device__ __forceinline__ void cpa16(void* smem, const void* gmem) {
    unsigned s = (unsigned)__cvta_generic_to_shared(smem);
    asm volatile("cp.async.cg.shared.global [%0], [%1], 16;" :: "r"(s), "l"(gmem));
}
__device__ __forceinline__ void cpa8(void* smem, const void* gmem) {
    unsigned s = (unsigned)__cvta_generic_to_shared(smem);
    asm volatile("cp.async.ca.shared.global [%0], [%1], 8;" :: "r"(s), "l"(gmem));
}
__device__ __forceinline__ void cpa_commit() {
    asm volatile("cp.async.commit_group;" ::: "memory");
}
__device__ __forceinline__ void cpa_wait0() {
    asm volatile("cp.async.wait_group 0;" ::: "memory");
}

// ---------------- kernel 1: register sliding-window conv + silu + l2norm ----------------
// One warp = one 128-chan head-block x 16-token strip. Lane owns 4 channels.
// 19 coalesced LDG.128 per thread (sliding window) -> 16 conv outputs in regs.
// NO shared memory. l2-norm = 5-shfl full-warp reduction per token.
// hb 0..15: q heads; 16..31: k heads; 32..63: v heads (no norm).
__global__ __launch_bounds__(256) void prep_kernel(
    const float* __restrict__ x,      // [NROWS, QKV]
    const float* __restrict__ w)      // [QKV, 4]
{
    const int gw   = (blockIdx.x * 256 + threadIdx.x) >> 5;  // global warp
    const int lane = threadIdx.x & 31;
    const int strip = gw & 127;              // 16-token strip
    const int hb    = (gw >> 7) & 63;        // head-block (128 channels)
    const int b     = gw >> 13;              // batch
    const int t0    = strip * 16;
    const int ch    = hb * 128 + lane * 4;

    const float* xp = x + (size_t)(b * S_LEN + t0) * QKV + ch;

    // per-channel taps: w4[ch+c] = (w[ch+c][0..3])
    const float4* w4 = (const float4*)w;
    const float4 wv0 = __ldg(w4 + ch + 0);
    const float4 wv1 = __ldg(w4 + ch + 1);
    const float4 wv2 = __ldg(w4 + ch + 2);
    const float4 wv3 = __ldg(w4 + ch + 3);

    // sliding window: rows t-3, t-2, t-1 (zero history before t=0)
    float4 h0 = make_float4(0.f, 0.f, 0.f, 0.f);
    float4 h1 = h0, h2 = h0;
    if (t0 >= 3) {
        h0 = *reinterpret_cast<const float4*>(xp - 3 * QKV);
        h1 = *reinterpret_cast<const float4*>(xp - 2 * QKV);
        h2 = *reinterpret_cast<const float4*>(xp - 1 * QKV);
    }

    float4 y[16];
#pragma unroll
    for (int t = 0; t < 16; t++) {
        const float4 xc = *reinterpret_cast<const float4*>(xp + (size_t)t * QKV);
        float4 a;
        a.x = fmaf(h0.x, wv0.x, fmaf(h1.x, wv0.y, fmaf(h2.x, wv0.z, xc.x * wv0.w)));
        a.y = fmaf(h0.y, wv1.x, fmaf(h1.y, wv1.y, fmaf(h2.y, wv1.z, xc.y * wv1.w)));
        a.z = fmaf(h0.z, wv2.x, fmaf(h1.z, wv2.y, fmaf(h2.z, wv2.z, xc.z * wv2.w)));
        a.w = fmaf(h0.w, wv3.x, fmaf(h1.w, wv3.y, fmaf(h2.w, wv3.z, xc.w * wv3.w)));
        // SiLU
        a.x = a.x / (1.f + __expf(-a.x));
        a.y = a.y / (1.f + __expf(-a.y));
        a.z = a.z / (1.f + __expf(-a.z));
        a.w = a.w / (1.f + __expf(-a.w));
        y[t] = a;
        h0 = h1; h1 = h2; h2 = xc;
    }

    const float qscale = 0.08838834764831845f; // 128^-0.5

    if (hb < 32) {
        // q/k: full-warp l2-norm per token, then scale + store
        const bool isq = hb < 16;
        const int head = isq ? hb : hb - 16;
        float* dbase = (isq ? g_qn : g_kn)
                     + ((size_t)(b * S_LEN + t0) * HK + head) * DK + lane * 4;
        const float sc = isq ? qscale : 1.f;
#pragma unroll
        for (int t = 0; t < 16; t++) {
            float4 a = y[t];
            float ss = a.x * a.x + a.y * a.y + a.z * a.z + a.w * a.w;
#pragma unroll
            for (int o = 16; o > 0; o >>= 1)
                ss += __shfl_xor_sync(0xffffffffu, ss, o);
            const float mul = rsqrtf(ss + 1e-6f) * sc;
            a.x *= mul; a.y *= mul; a.z *= mul; a.w *= mul;
            *reinterpret_cast<float4*>(dbase + (size_t)t * (HK * DK)) = a;
        }
    } else {
        const int head = hb - 32;
        float* dbase = g_v + ((size_t)(b * S_LEN + t0) * HV + head) * DV + lane * 4;
#pragma unroll
        for (int t = 0; t < 16; t++)
            *reinterpret_cast<float4*>(dbase + (size_t)t * (HV * DV)) = y[t];
    }
}

// ---------------- kernel 1b: gating ----------------
__global__ __launch_bounds__(256) void gate_kernel(
    const float* __restrict__ bvec,   // [NROWS, HV]
    const float* __restrict__ avec,   // [NROWS, HV]
    const float* __restrict__ dt_bias,// [HV]
    const float* __restrict__ alog)   // [HV]
{
    const int idx = blockIdx.x * 256 + threadIdx.x;   // < NROWS*HV = 131072
    const int h = idx & 31;
    float aa = avec[idx] + __ldg(dt_bias + h);
    float sp = (aa > 20.f) ? aa : log1pf(expf(aa));
    float g  = -expf(__ldg(alog + h)) * sp;
    float eg = expf(g);
    float bb = bvec[idx];
    float beta = 1.f / (1.f + expf(-bb));
    *reinterpret_cast<float2*>(g_gate + (size_t)idx * 2) = make_float2(eg, beta);
}

// ---------------- kernel 2: gated delta-rule recurrence ----------------
// grid 128 = (b, h, vh). 256 threads = 32 column-PAIRS x 8 k-slices of 16 dims.
// Thread (c2, p): state S[16p..16p+16, {2c2, 2c2+1}] as 2x8 packed f32x2.
// cp.async staging; kr double-buffered in registers (LDS off the critical chain).
// Owner-split butterfly reductions; output reduction deferred one token.
__global__ __launch_bounds__(256, 1) void rec_kernel(float* __restrict__ out)
{
    const int blk = blockIdx.x;
    const int b   = blk >> 6;
    const int h   = (blk >> 1) & 31;
    const int vh  = blk & 1;
    const int hk  = h >> 1;

    const int tid = threadIdx.x;
    const int c2  = tid >> 3;          // column pair 0..31
    const int p   = tid & 7;           // k-slice 0..7 (16 dims)
    const bool lowp = (p < 4);

    __shared__ float sk[2][TB][8][20];   // 8 groups x 16 floats pad 20: conflict-free
    __shared__ float sq[2][TB][8][20];
    __shared__ float sv[2][TB][64];
    __shared__ float2 sg[2][TB];

    ull s0[8], s1[8];
#pragma unroll
    for (int i = 0; i < 8; i++) { s0[i] = 0ull; s1[i] = 0ull; }

    const float* kbase = g_kn + ((size_t)(b * S_LEN) * HK + hk) * DK;
    const float* qbase = g_qn + ((size_t)(b * S_LEN) * HK + hk) * DK;
    const float* vbase = g_v  + ((size_t)(b * S_LEN) * HV + h) * DV + vh * 64;
    const float* gbase = g_gate + ((size_t)(b * S_LEN) * HV + h) * 2;
    const size_t qk_stride = (size_t)HK * DK;
    const size_t v_stride  = (size_t)HV * DV;

    auto load_batch = [&](int buf, int t0) {
#pragma unroll
        for (int rep = 0; rep < 2; rep++) {
            int i  = tid + rep * 256;
            int tt = i >> 5, j = i & 31;
            cpa16(&sk[buf][tt][j >> 2][(j & 3) * 4],
                  kbase + (size_t)(t0 + tt) * qk_stride + j * 4);
            cpa16(&sq[buf][tt][j >> 2][(j & 3) * 4],
                  qbase + (size_t)(t0 + tt) * qk_stride + j * 4);
        }
        {
            int tt = tid >> 4, j = tid & 15;
            cpa16(&sv[buf][tt][j * 4],
                  vbase + (size_t)(t0 + tt) * v_stride + j * 4);
        }
        if (tid < TB)
            cpa8(&sg[buf][tid], gbase + (size_t)(t0 + tid) * (HV * 2));
        cpa_commit();
    };

    load_batch(0, 0);
    cpa_wait0();
    __syncthreads();
    int buf = 0;

    float* obase = out + ((size_t)(b * S_LEN) * HV + h) * DV + vh * 64 + c2 * 2;
    const int osel = lowp ? 0 : 1;

    float oo_m = 0.f, oo_o = 0.f;      // prev token's output partials (owner-split)

    F4U krA[4], krB[4];

#define LOADK(dst, bufv, ttv) do {                                            \
    const float* _kp = &sk[bufv][ttv][p][0];                                  \
    dst[0].f = *reinterpret_cast<const float4*>(_kp + 0);                     \
    dst[1].f = *reinterpret_cast<const float4*>(_kp + 4);                     \
    dst[2].f = *reinterpret_cast<const float4*>(_kp + 8);                     \
    dst[3].f = *reinterpret_cast<const float4*>(_kp + 12);                    \
} while (0)

#define BODY(kr, TT, T) do {                                                  \
    const float2 g2 = sg[buf][TT];                                            \
    const float eg = g2.x, beta = g2.y;                                       \
    ull pa0 = 0, pa1 = 0, pb0 = 0, pb1 = 0;                                   \
    _Pragma("unroll")                                                         \
    for (int i = 0; i < 4; i++) {                                             \
        FMA2(pa0, kr[i].u[0], s0[2*i],   pa0);                                \
        FMA2(pa1, kr[i].u[1], s0[2*i+1], pa1);                                \
        FMA2(pb0, kr[i].u[0], s1[2*i],   pb0);                                \
        FMA2(pb1, kr[i].u[1], s1[2*i+1], pb1);                                \
    }                                                                         \
    const ull egp = pack2(eg, eg);                                            \
    _Pragma("unroll")                                                         \
    for (int i = 0; i < 8; i++) { MUL2(s0[i], s0[i], egp); MUL2(s1[i], s1[i], egp); } \
    ull pA, pB;                                                               \
    ADD2(pA, pa0, pa1);                                                       \
    ADD2(pB, pb0, pb1);                                                       \
    float2 fA = unpack2(pA), fB = unpack2(pB);                                \
    const float p0 = fA.x + fA.y;                                             \
    const float p1 = fB.x + fB.y;                                             \
    float mine  = lowp ? p0 : p1;                                             \
    float other = lowp ? p1 : p0;                                             \
    mine += __shfl_xor_sync(0xffffffffu, other, 4);                           \
    oo_m += __shfl_xor_sync(0xffffffffu, oo_o,  4);                           \
    mine += __shfl_xor_sync(0xffffffffu, mine, 1);                            \
    oo_m += __shfl_xor_sync(0xffffffffu, oo_m,  1);                           \
    mine += __shfl_xor_sync(0xffffffffu, mine, 2);                            \
    oo_m += __shfl_xor_sync(0xffffffffu, oo_m,  2);                           \
    const float both = __shfl_xor_sync(0xffffffffu, mine, 4);                 \
    if ((T) != 0 && (p & 3) == 0)                                             \
        obase[(size_t)((T) - 1) * v_stride + osel] = oo_m;                    \
    const float pred0 = lowp ? mine : both;                                   \
    const float pred1 = lowp ? both : mine;                                   \
    const float2 v2 = *reinterpret_cast<const float2*>(&sv[buf][TT][c2 * 2]); \
    const float u0 = beta * (v2.x - eg * pred0);                              \
    const float u1 = beta * (v2.y - eg * pred1);                              \
    const ull up0 = pack2(u0, u0), up1 = pack2(u1, u1);                       \
    _Pragma("unroll")                                                         \
    for (int i = 0; i < 4; i++) {                                             \
        FMA2(s0[2*i],   kr[i].u[0], up0, s0[2*i]);                            \
        FMA2(s0[2*i+1], kr[i].u[1], up0, s0[2*i+1]);                          \
        FMA2(s1[2*i],   kr[i].u[0], up1, s1[2*i]);                            \
        FMA2(s1[2*i+1], kr[i].u[1], up1, s1[2*i+1]);                          \
    }                                                                         \
    F4U qr[4];                                                                \
    const float* qp = &sq[buf][TT][p][0];                                     \
    _Pragma("unroll")                                                         \
    for (int i = 0; i < 4; i++)                                               \
        qr[i].f = *reinterpret_cast<const float4*>(qp + i * 4);               \
    ull qa0 = 0, qa1 = 0, qb0 = 0, qb1 = 0;                                   \
    _Pragma("unroll")                                                         \
    for (int i = 0; i < 4; i++) {                                             \
        FMA2(qa0, qr[i].u[0], s0[2*i],   qa0);                                \
        FMA2(qa1, qr[i].u[1], s0[2*i+1], qa1);                                \
        FMA2(qb0, qr[i].u[0], s1[2*i],   qb0);                                \
        FMA2(qb1, qr[i].u[1], s1[2*i+1], qb1);                                \
    }                                                                         \
    ull qA, qB;                                                               \
    ADD2(qA, qa0, qa1);                                                       \
    ADD2(qB, qb0, qb1);                                                       \
    float2 gA = unpack2(qA), gB = unpack2(qB);                                \
    const float q0 = gA.x + gA.y;                                             \
    const float q1 = gB.x + gB.y;                                             \
    oo_m = lowp ? q0 : q1;                                                    \
    oo_o = lowp ? q1 : q0;                                                    \
} while (0)

#pragma unroll 1
    for (int t0 = 0; t0 < S_LEN; t0 += TB) {
        if (t0 + TB < S_LEN) load_batch(buf ^ 1, t0 + TB);

        LOADK(krA, buf, 0);
#pragma unroll 2
        for (int tt = 0; tt < TB; tt += 2) {
            LOADK(krB, buf, tt + 1);
            BODY(krA, tt, t0 + tt);
            {
                int tn = tt + 2; if (tn > TB - 1) tn = TB - 1;
                LOADK(krA, buf, tn);
            }
            BODY(krB, tt + 1, t0 + tt + 1);
        }

        cpa_wait0();
        __syncthreads();
        buf ^= 1;
    }

    // drain: reduce and store the final token's output
    {
        oo_m += __shfl_xor_sync(0xffffffffu, oo_o, 4);
        oo_m += __shfl_xor_sync(0xffffffffu, oo_m, 1);
        oo_m += __shfl_xor_sync(0xffffffffu, oo_m, 2);
        if ((p & 3) == 0)
            obase[(size_t)(S_LEN - 1) * v_stride + osel] = oo_m;
    }
#undef LOADK
#undef BODY
}

// ---------------- launch ----------------
extern "C" void kernel_launch(void* const* d_in, const int* in_sizes, int n_in,
                              void* d_out, int out_size)
{
    const float* mixed_qkv = (const float*)d_in[0];
    const float* bvec      = (const float*)d_in[1];
    const float* avec      = (const float*)d_in[2];
    const float* convw     = (const float*)d_in[3];
    const float* dt_bias   = (const float*)d_in[4];
    const float* alog      = (const float*)d_in[5];
    float* out = (float*)d_out;

    // 64 head-blocks x 128 strips x 2 batches = 16384 warps = 2048 blocks
    prep_kernel<<<2048, 256>>>(mixed_qkv, convw);
    gate_kernel<<<NROWS * HV / 256, 256>>>(bvec, avec, dt_bias, alog);
    rec_kernel<<<BQ * HV * 2, 256>>>(out);
}

// round 11
// speedup vs baseline: 1.8859x; 1.0419x over previous
#include <cuda_runtime.h>
#include <cuda_bf16.h>
#include <math.h>

#define BQ 2
#define S_LEN 2048
#define HK 16
#define HV 32
#define DK 128
#define DV 128
#define QKV 8192
#define NROWS (BQ * S_LEN)
#define TB 16   // tokens per smem staging batch (rec)

typedef unsigned long long ull;

// ---------------- scratch (device globals; no runtime allocation) ----------------
__device__ float g_qn[(size_t)NROWS * HK * DK];    // l2norm(q) * scale
__device__ float g_kn[(size_t)NROWS * HK * DK];    // l2norm(k)
__device__ float g_v [(size_t)NROWS * HV * DV];
__device__ float g_gate[(size_t)NROWS * HV * 2];   // float2 per (row,h): eg, beta

// ---------------- packed f32x2 helpers ----------------
__device__ __forceinline__ ull pack2(float lo, float hi) {
    ull r;
    asm("mov.b64 %0, {%1,%2};" : "=l"(r) : "f"(lo), "f"(hi));
    return r;
}
__device__ __forceinline__ float2 unpack2(ull v) {
    float2 r;
    asm("mov.b64 {%0,%1}, %2;" : "=f"(r.x), "=f"(r.y) : "l"(v));
    return r;
}
#define FMA2(d, a, b, c) asm("fma.rn.f32x2 %0, %1, %2, %3;" : "=l"(d) : "l"(a), "l"(b), "l"(c))
#define MUL2(d, a, b)    asm("mul.rn.f32x2 %0, %1, %2;"     : "=l"(d) : "l"(a), "l"(b))
#define ADD2(d, a, b)    asm("add.rn.f32x2 %0, %1, %2;"     : "=l"(d) : "l"(a), "l"(b))

union F4U { float4 f; ull u[2]; };

// ---------------- cp.async helpers ----------------
__device__ __forceinline__ void cpa16(void* smem, const void* gmem) {
    unsigned s = (unsigned)__cvta_generic_to_shared(smem);
    asm volatile("cp.async.cg.shared.global [%0], [%1], 16;" :: "r"(s), "l"(gmem));
}
__device__ __forceinline__ void cpa8(void* smem, const void* gmem) {
    unsigned s = (unsigned)__cvta_generic_to_shared(smem);
    asm volatile("cp.async.ca.shared.global [%0], [%1], 8;" :: "r"(s), "l"(gmem));
}
__device__ __forceinline__ void cpa_commit() {
    asm volatile("cp.async.commit_group;" ::: "memory");
}
__device__ __forceinline__ void cpa_wait0() {
    asm volatile("cp.async.wait_group 0;" ::: "memory");
}

// ---------------- kernel 1: register sliding-window conv + silu + l2norm ----------------
// One warp = one 128-chan head-block x 16-token strip. Lane owns 4 channels.
// Grouped streaming: 4 tokens live at a time (low regs -> 4 blocks/SM).
__global__ __launch_bounds__(256) void prep_kernel(
    const float* __restrict__ x,      // [NROWS, QKV]
    const float* __restrict__ w)      // [QKV, 4]
{
    const int gw   = (blockIdx.x * 256 + threadIdx.x) >> 5;  // global warp
    const int lane = threadIdx.x & 31;
    const int strip = gw & 127;              // 16-token strip
    const int hb    = (gw >> 7) & 63;        // head-block (128 channels)
    const int b     = gw >> 13;              // batch
    const int t0    = strip * 16;
    const int ch    = hb * 128 + lane * 4;

    const float* xp = x + (size_t)(b * S_LEN + t0) * QKV + ch;

    const float4* w4 = (const float4*)w;
    const float4 wv0 = __ldg(w4 + ch + 0);
    const float4 wv1 = __ldg(w4 + ch + 1);
    const float4 wv2 = __ldg(w4 + ch + 2);
    const float4 wv3 = __ldg(w4 + ch + 3);

    float4 h0 = make_float4(0.f, 0.f, 0.f, 0.f);
    float4 h1 = h0, h2 = h0;
    if (t0 >= 3) {
        h0 = *reinterpret_cast<const float4*>(xp - 3 * QKV);
        h1 = *reinterpret_cast<const float4*>(xp - 2 * QKV);
        h2 = *reinterpret_cast<const float4*>(xp - 1 * QKV);
    }

    const float qscale = 0.08838834764831845f; // 128^-0.5

#define CONV_STEP(a, T) do {                                                        \
    const float4 xc = *reinterpret_cast<const float4*>(xp + (size_t)(T) * QKV);    \
    a.x = fmaf(h0.x, wv0.x, fmaf(h1.x, wv0.y, fmaf(h2.x, wv0.z, xc.x * wv0.w)));   \
    a.y = fmaf(h0.y, wv1.x, fmaf(h1.y, wv1.y, fmaf(h2.y, wv1.z, xc.y * wv1.w)));   \
    a.z = fmaf(h0.z, wv2.x, fmaf(h1.z, wv2.y, fmaf(h2.z, wv2.z, xc.z * wv2.w)));   \
    a.w = fmaf(h0.w, wv3.x, fmaf(h1.w, wv3.y, fmaf(h2.w, wv3.z, xc.w * wv3.w)));   \
    a.x = a.x / (1.f + __expf(-a.x));                                              \
    a.y = a.y / (1.f + __expf(-a.y));                                              \
    a.z = a.z / (1.f + __expf(-a.z));                                              \
    a.w = a.w / (1.f + __expf(-a.w));                                              \
    h0 = h1; h1 = h2; h2 = xc;                                                     \
} while (0)

    if (hb < 32) {
        const bool isq = hb < 16;
        const int head = isq ? hb : hb - 16;
        float* dbase = (isq ? g_qn : g_kn)
                     + ((size_t)(b * S_LEN + t0) * HK + head) * DK + lane * 4;
        const float sc = isq ? qscale : 1.f;
#pragma unroll
        for (int g = 0; g < 4; g++) {
            float4 yb[4];
#pragma unroll
            for (int tt = 0; tt < 4; tt++) CONV_STEP(yb[tt], g * 4 + tt);
#pragma unroll
            for (int tt = 0; tt < 4; tt++) {
                float4 a = yb[tt];
                float ss = a.x * a.x + a.y * a.y + a.z * a.z + a.w * a.w;
#pragma unroll
                for (int o = 16; o > 0; o >>= 1)
                    ss += __shfl_xor_sync(0xffffffffu, ss, o);
                const float mul = rsqrtf(ss + 1e-6f) * sc;
                a.x *= mul; a.y *= mul; a.z *= mul; a.w *= mul;
                *reinterpret_cast<float4*>(
                    dbase + (size_t)(g * 4 + tt) * (HK * DK)) = a;
            }
        }
    } else {
        const int head = hb - 32;
        float* dbase = g_v + ((size_t)(b * S_LEN + t0) * HV + head) * DV + lane * 4;
#pragma unroll
        for (int t = 0; t < 16; t++) {
            float4 a;
            CONV_STEP(a, t);
            *reinterpret_cast<float4*>(dbase + (size_t)t * (HV * DV)) = a;
        }
    }
#undef CONV_STEP
}

// ---------------- kernel 1b: gating ----------------
__global__ __launch_bounds__(256) void gate_kernel(
    const float* __restrict__ bvec,   // [NROWS, HV]
    const float* __restrict__ avec,   // [NROWS, HV]
    const float* __restrict__ dt_bias,// [HV]
    const float* __restrict__ alog)   // [HV]
{
    const int idx = blockIdx.x * 256 + threadIdx.x;   // < NROWS*HV = 131072
    const int h = idx & 31;
    float aa = avec[idx] + __ldg(dt_bias + h);
    float sp = (aa > 20.f) ? aa : log1pf(expf(aa));
    float g  = -expf(__ldg(alog + h)) * sp;
    float eg = expf(g);
    float bb = bvec[idx];
    float beta = 1.f / (1.f + expf(-bb));
    *reinterpret_cast<float2*>(g_gate + (size_t)idx * 2) = make_float2(eg, beta);
}

// ---------------- kernel 2: gated delta-rule recurrence ----------------
// grid 128 = (b, h, vh). 256 threads = 32 column-PAIRS x 8 k-slices of 16 dims.
// OWNED/OTHER state layout: lane's so[] = state dims of its OWNED column
// (lowp -> col0, highp -> col1), sx[] = the other column. After the 3-shfl
// pred reduction, u_own is computed and so[] updated IMMEDIATELY (no divergence,
// overlaps the 4th shfl that exchanges u); sx[] updates after the exchange.
// cp.async staging; kr register double-buffer; output reduction deferred 1 token.
__global__ __launch_bounds__(256, 1) void rec_kernel(float* __restrict__ out)
{
    const int blk = blockIdx.x;
    const int b   = blk >> 6;
    const int h   = (blk >> 1) & 31;
    const int vh  = blk & 1;
    const int hk  = h >> 1;

    const int tid = threadIdx.x;
    const int c2  = tid >> 3;          // column pair 0..31
    const int p   = tid & 7;           // k-slice 0..7 (16 dims)
    const bool lowp = (p < 4);

    __shared__ float sk[2][TB][8][20];   // 8 groups x 16 floats pad 20: conflict-free
    __shared__ float sq[2][TB][8][20];
    __shared__ float sv[2][TB][64];
    __shared__ float2 sg[2][TB];

    ull so[8], sx[8];                  // owned-column / other-column state
#pragma unroll
    for (int i = 0; i < 8; i++) { so[i] = 0ull; sx[i] = 0ull; }

    const float* kbase = g_kn + ((size_t)(b * S_LEN) * HK + hk) * DK;
    const float* qbase = g_qn + ((size_t)(b * S_LEN) * HK + hk) * DK;
    const float* vbase = g_v  + ((size_t)(b * S_LEN) * HV + h) * DV + vh * 64;
    const float* gbase = g_gate + ((size_t)(b * S_LEN) * HV + h) * 2;
    const size_t qk_stride = (size_t)HK * DK;
    const size_t v_stride  = (size_t)HV * DV;

    auto load_batch = [&](int buf, int t0) {
#pragma unroll
        for (int rep = 0; rep < 2; rep++) {
            int i  = tid + rep * 256;
            int tt = i >> 5, j = i & 31;
            cpa16(&sk[buf][tt][j >> 2][(j & 3) * 4],
                  kbase + (size_t)(t0 + tt) * qk_stride + j * 4);
            cpa16(&sq[buf][tt][j >> 2][(j & 3) * 4],
                  qbase + (size_t)(t0 + tt) * qk_stride + j * 4);
        }
        {
            int tt = tid >> 4, j = tid & 15;
            cpa16(&sv[buf][tt][j * 4],
                  vbase + (size_t)(t0 + tt) * v_stride + j * 4);
        }
        if (tid < TB)
            cpa8(&sg[buf][tid], gbase + (size_t)(t0 + tid) * (HV * 2));
        cpa_commit();
    };

    load_batch(0, 0);
    cpa_wait0();
    __syncthreads();
    int buf = 0;

    float* obase = out + ((size_t)(b * S_LEN) * HV + h) * DV + vh * 64 + c2 * 2;
    const int osel = lowp ? 0 : 1;     // owned column index within the pair

    float oo_m = 0.f, oo_o = 0.f;      // prev token's output partials (own/other)

    F4U krA[4], krB[4];

#define LOADK(dst, bufv, ttv) do {                                            \
    const float* _kp = &sk[bufv][ttv][p][0];                                  \
    dst[0].f = *reinterpret_cast<const float4*>(_kp + 0);                     \
    dst[1].f = *reinterpret_cast<const float4*>(_kp + 4);                     \
    dst[2].f = *reinterpret_cast<const float4*>(_kp + 8);                     \
    dst[3].f = *reinterpret_cast<const float4*>(_kp + 12);                    \
} while (0)

#define BODY(kr, TT, T) do {                                                  \
    const float2 g2 = sg[buf][TT];                                            \
    const float eg = g2.x, beta = g2.y;                                       \
    ull pa0 = 0, pa1 = 0, pb0 = 0, pb1 = 0;                                   \
    _Pragma("unroll")                                                         \
    for (int i = 0; i < 4; i++) {                                             \
        FMA2(pa0, kr[i].u[0], so[2*i],   pa0);                                \
        FMA2(pa1, kr[i].u[1], so[2*i+1], pa1);                                \
        FMA2(pb0, kr[i].u[0], sx[2*i],   pb0);                                \
        FMA2(pb1, kr[i].u[1], sx[2*i+1], pb1);                                \
    }                                                                         \
    const ull egp = pack2(eg, eg);                                            \
    _Pragma("unroll")                                                         \
    for (int i = 0; i < 8; i++) { MUL2(so[i], so[i], egp); MUL2(sx[i], sx[i], egp); } \
    ull pA, pB;                                                               \
    ADD2(pA, pa0, pa1);                                                       \
    ADD2(pB, pb0, pb1);                                                       \
    float2 fA = unpack2(pA), fB = unpack2(pB);                                \
    float mine = fA.x + fA.y;          /* owned-col partial */                 \
    const float oth = fB.x + fB.y;     /* other-col partial */                 \
    mine += __shfl_xor_sync(0xffffffffu, oth,  4);                            \
    oo_m += __shfl_xor_sync(0xffffffffu, oo_o, 4);                            \
    mine += __shfl_xor_sync(0xffffffffu, mine, 1);                            \
    oo_m += __shfl_xor_sync(0xffffffffu, oo_m, 1);                            \
    mine += __shfl_xor_sync(0xffffffffu, mine, 2);                            \
    oo_m += __shfl_xor_sync(0xffffffffu, oo_m, 2);                            \
    if ((T) != 0 && (p & 3) == 0)                                             \
        obase[(size_t)((T) - 1) * v_stride + osel] = oo_m;                    \
    const float2 v2 = *reinterpret_cast<const float2*>(&sv[buf][TT][c2 * 2]); \
    const float v_own = lowp ? v2.x : v2.y;                                   \
    const float u_own = beta * (v_own - eg * mine);                           \
    const float u_oth = __shfl_xor_sync(0xffffffffu, u_own, 4);               \
    const ull upo = pack2(u_own, u_own);                                      \
    _Pragma("unroll")                                                         \
    for (int i = 0; i < 4; i++) {      /* owned update: overlaps the shfl */  \
        FMA2(so[2*i],   kr[i].u[0], upo, so[2*i]);                            \
        FMA2(so[2*i+1], kr[i].u[1], upo, so[2*i+1]);                          \
    }                                                                         \
    const ull upx = pack2(u_oth, u_oth);                                      \
    _Pragma("unroll")                                                         \
    for (int i = 0; i < 4; i++) {                                             \
        FMA2(sx[2*i],   kr[i].u[0], upx, sx[2*i]);                            \
        FMA2(sx[2*i+1], kr[i].u[1], upx, sx[2*i+1]);                          \
    }                                                                         \
    F4U qr[4];                                                                \
    const float* qp = &sq[buf][TT][p][0];                                     \
    _Pragma("unroll")                                                         \
    for (int i = 0; i < 4; i++)                                               \
        qr[i].f = *reinterpret_cast<const float4*>(qp + i * 4);               \
    ull qa0 = 0, qa1 = 0, qb0 = 0, qb1 = 0;                                   \
    _Pragma("unroll")                                                         \
    for (int i = 0; i < 4; i++) {                                             \
        FMA2(qa0, qr[i].u[0], so[2*i],   qa0);                                \
        FMA2(qa1, qr[i].u[1], so[2*i+1], qa1);                                \
        FMA2(qb0, qr[i].u[0], sx[2*i],   qb0);                                \
        FMA2(qb1, qr[i].u[1], sx[2*i+1], qb1);                                \
    }                                                                         \
    ull qA, qB;                                                               \
    ADD2(qA, qa0, qa1);                                                       \
    ADD2(qB, qb0, qb1);                                                       \
    float2 gA = unpack2(qA), gB = unpack2(qB);                                \
    oo_m = gA.x + gA.y;                /* owned-col output partial */          \
    oo_o = gB.x + gB.y;                /* other-col output partial */          \
} while (0)

#pragma unroll 1
    for (int t0 = 0; t0 < S_LEN; t0 += TB) {
        if (t0 + TB < S_LEN) load_batch(buf ^ 1, t0 + TB);

        LOADK(krA, buf, 0);
#pragma unroll 2
        for (int tt = 0; tt < TB; tt += 2) {
            LOADK(krB, buf, tt + 1);
            BODY(krA, tt, t0 + tt);
            {
                int tn = tt + 2; if (tn > TB - 1) tn = TB - 1;
                LOADK(krA, buf, tn);
            }
            BODY(krB, tt + 1, t0 + tt + 1);
        }

        cpa_wait0();
        __syncthreads();
        buf ^= 1;
    }

    // drain: reduce and store the final token's output
    {
        oo_m += __shfl_xor_sync(0xffffffffu, oo_o, 4);
        oo_m += __shfl_xor_sync(0xffffffffu, oo_m, 1);
        oo_m += __shfl_xor_sync(0xffffffffu, oo_m, 2);
        if ((p & 3) == 0)
            obase[(size_t)(S_LEN - 1) * v_stride + osel] = oo_m;
    }
#undef LOADK
#undef BODY
}

// ---------------- launch ----------------
extern "C" void kernel_launch(void* const* d_in, const int* in_sizes, int n_in,
                              void* d_out, int out_size)
{
    const float* mixed_qkv = (const float*)d_in[0];
    const float* bvec      = (const float*)d_in[1];
    const float* avec      = (const float*)d_in[2];
    const float* convw     = (const float*)d_in[3];
    const float* dt_bias   = (const float*)d_in[4];
    const float* alog      = (const float*)d_in[5];
    float* out = (float*)d_out;

    prep_kernel<<<2048, 256>>>(mixed_qkv, convw);
    gate_kernel<<<NROWS * HV / 256, 256>>>(bvec, avec, dt_bias, alog);
    rec_kernel<<<BQ * HV * 2, 256>>>(out);
}

// round 12
// speedup vs baseline: 2.0269x; 1.0747x over previous
#include <cuda_runtime.h>
#include <cuda_bf16.h>
#include <math.h>

#define BQ 2
#define S_LEN 2048
#define HK 16
#define HV 32
#define DK 128
#define DV 128
#define QKV 8192
#define NROWS (BQ * S_LEN)
#define TB 16   // tokens per smem staging batch (rec); 8 pairs

typedef unsigned long long ull;

// ---------------- scratch (device globals; no runtime allocation) ----------------
__device__ float g_qn[(size_t)NROWS * HK * DK];    // l2norm(q) * scale
__device__ float g_kn[(size_t)NROWS * HK * DK];    // l2norm(k)
__device__ float g_v [(size_t)NROWS * HV * DV];
__device__ float g_gate[(size_t)NROWS * HV * 2];   // float2 per (row,h): eg, beta
__device__ float2 g_cross[(size_t)BQ * (S_LEN / 2) * HK];  // per (b,tp,hk): (k1.k2, q1.k1)

// ---------------- packed f32x2 helpers ----------------
__device__ __forceinline__ ull pack2(float lo, float hi) {
    ull r;
    asm("mov.b64 %0, {%1,%2};" : "=l"(r) : "f"(lo), "f"(hi));
    return r;
}
__device__ __forceinline__ float2 unpack2(ull v) {
    float2 r;
    asm("mov.b64 {%0,%1}, %2;" : "=f"(r.x), "=f"(r.y) : "l"(v));
    return r;
}
#define FMA2(d, a, b, c) asm("fma.rn.f32x2 %0, %1, %2, %3;" : "=l"(d) : "l"(a), "l"(b), "l"(c))
#define MUL2(d, a, b)    asm("mul.rn.f32x2 %0, %1, %2;"     : "=l"(d) : "l"(a), "l"(b))
#define ADD2(d, a, b)    asm("add.rn.f32x2 %0, %1, %2;"     : "=l"(d) : "l"(a), "l"(b))

union F4U { float4 f; ull u[2]; };

// ---------------- cp.async helpers ----------------
__device__ __forceinline__ void cpa16(void* smem, const void* gmem) {
    unsigned s = (unsigned)__cvta_generic_to_shared(smem);
    asm volatile("cp.async.cg.shared.global [%0], [%1], 16;" :: "r"(s), "l"(gmem));
}
__device__ __forceinline__ void cpa8(void* smem, const void* gmem) {
    unsigned s = (unsigned)__cvta_generic_to_shared(smem);
    asm volatile("cp.async.ca.shared.global [%0], [%1], 8;" :: "r"(s), "l"(gmem));
}
__device__ __forceinline__ void cpa_commit() {
    asm volatile("cp.async.commit_group;" ::: "memory");
}
__device__ __forceinline__ void cpa_wait0() {
    asm volatile("cp.async.wait_group 0;" ::: "memory");
}

// ---------------- kernel 1: register sliding-window conv + silu + l2norm ----------------
// One warp = one 128-chan head-block x 16-token strip. Lane owns 4 channels.
// Inline per-token reduce+store (minimal live registers -> 4 blocks/SM).
__global__ __launch_bounds__(256) void prep_kernel(
    const float* __restrict__ x,      // [NROWS, QKV]
    const float* __restrict__ w)      // [QKV, 4]
{
    const int gw   = (blockIdx.x * 256 + threadIdx.x) >> 5;  // global warp
    const int lane = threadIdx.x & 31;
    const int strip = gw & 127;              // 16-token strip
    const int hb    = (gw >> 7) & 63;        // head-block (128 channels)
    const int b     = gw >> 13;              // batch
    const int t0    = strip * 16;
    const int ch    = hb * 128 + lane * 4;

    const float* xp = x + (size_t)(b * S_LEN + t0) * QKV + ch;

    const float4* w4 = (const float4*)w;
    const float4 wv0 = __ldg(w4 + ch + 0);
    const float4 wv1 = __ldg(w4 + ch + 1);
    const float4 wv2 = __ldg(w4 + ch + 2);
    const float4 wv3 = __ldg(w4 + ch + 3);

    float4 h0 = make_float4(0.f, 0.f, 0.f, 0.f);
    float4 h1 = h0, h2 = h0;
    if (t0 >= 3) {
        h0 = *reinterpret_cast<const float4*>(xp - 3 * QKV);
        h1 = *reinterpret_cast<const float4*>(xp - 2 * QKV);
        h2 = *reinterpret_cast<const float4*>(xp - 1 * QKV);
    }

    const float qscale = 0.08838834764831845f; // 128^-0.5

#define CONV_STEP(a, T) do {                                                        \
    const float4 xc = *reinterpret_cast<const float4*>(xp + (size_t)(T) * QKV);    \
    a.x = fmaf(h0.x, wv0.x, fmaf(h1.x, wv0.y, fmaf(h2.x, wv0.z, xc.x * wv0.w)));   \
    a.y = fmaf(h0.y, wv1.x, fmaf(h1.y, wv1.y, fmaf(h2.y, wv1.z, xc.y * wv1.w)));   \
    a.z = fmaf(h0.z, wv2.x, fmaf(h1.z, wv2.y, fmaf(h2.z, wv2.z, xc.z * wv2.w)));   \
    a.w = fmaf(h0.w, wv3.x, fmaf(h1.w, wv3.y, fmaf(h2.w, wv3.z, xc.w * wv3.w)));   \
    a.x = a.x / (1.f + __expf(-a.x));                                              \
    a.y = a.y / (1.f + __expf(-a.y));                                              \
    a.z = a.z / (1.f + __expf(-a.z));                                              \
    a.w = a.w / (1.f + __expf(-a.w));                                              \
    h0 = h1; h1 = h2; h2 = xc;                                                     \
} while (0)

    if (hb < 32) {
        const bool isq = hb < 16;
        const int head = isq ? hb : hb - 16;
        float* dbase = (isq ? g_qn : g_kn)
                     + ((size_t)(b * S_LEN + t0) * HK + head) * DK + lane * 4;
        const float sc = isq ? qscale : 1.f;
#pragma unroll
        for (int t = 0; t < 16; t++) {
            float4 a;
            CONV_STEP(a, t);
            float ss = a.x * a.x + a.y * a.y + a.z * a.z + a.w * a.w;
#pragma unroll
            for (int o = 16; o > 0; o >>= 1)
                ss += __shfl_xor_sync(0xffffffffu, ss, o);
            const float mul = rsqrtf(ss + 1e-6f) * sc;
            a.x *= mul; a.y *= mul; a.z *= mul; a.w *= mul;
            *reinterpret_cast<float4*>(dbase + (size_t)t * (HK * DK)) = a;
        }
    } else {
        const int head = hb - 32;
        float* dbase = g_v + ((size_t)(b * S_LEN + t0) * HV + head) * DV + lane * 4;
#pragma unroll
        for (int t = 0; t < 16; t++) {
            float4 a;
            CONV_STEP(a, t);
            *reinterpret_cast<float4*>(dbase + (size_t)t * (HV * DV)) = a;
        }
    }
#undef CONV_STEP
}

// ---------------- kernel 1b: gating ----------------
__global__ __launch_bounds__(256) void gate_kernel(
    const float* __restrict__ bvec,
    const float* __restrict__ avec,
    const float* __restrict__ dt_bias,
    const float* __restrict__ alog)
{
    const int idx = blockIdx.x * 256 + threadIdx.x;   // < NROWS*HV
    const int h = idx & 31;
    float aa = avec[idx] + __ldg(dt_bias + h);
    float sp = (aa > 20.f) ? aa : log1pf(expf(aa));
    float g  = -expf(__ldg(alog + h)) * sp;
    float eg = expf(g);
    float bb = bvec[idx];
    float beta = 1.f / (1.f + expf(-bb));
    *reinterpret_cast<float2*>(g_gate + (size_t)idx * 2) = make_float2(eg, beta);
}

// ---------------- kernel 1c: pair cross-scalars (k1.k2, q1.k1) ----------------
// One warp per (b, hk, token-pair). Reads normalized q/k from scratch.
__global__ __launch_bounds__(256) void cross_kernel()
{
    const int gw   = blockIdx.x * 8 + (threadIdx.x >> 5);   // 32768 warps
    const int lane = threadIdx.x & 31;
    const int b  = gw >> 14;
    const int hk = (gw >> 10) & 15;
    const int tp = gw & 1023;

    const size_t base = ((size_t)(b * S_LEN + 2 * tp) * HK + hk) * DK + lane * 4;
    const float4 k1 = *reinterpret_cast<const float4*>(g_kn + base);
    const float4 k2 = *reinterpret_cast<const float4*>(g_kn + base + HK * DK);
    const float4 q1 = *reinterpret_cast<const float4*>(g_qn + base);

    float ck = k1.x * k2.x + k1.y * k2.y + k1.z * k2.z + k1.w * k2.w;
    float qk = q1.x * k1.x + q1.y * k1.y + q1.z * k1.z + q1.w * k1.w;
#pragma unroll
    for (int o = 16; o > 0; o >>= 1) {
        ck += __shfl_xor_sync(0xffffffffu, ck, o);
        qk += __shfl_xor_sync(0xffffffffu, qk, o);
    }
    if (lane == 0)
        g_cross[(size_t)(b * (S_LEN / 2) + tp) * HK + hk] = make_float2(ck, qk);
}

// ---------------- kernel 2: rank-2 (paired-token) gated delta-rule ----------------
// grid 128 = (b, h, vh). 256 threads = 32 column-pairs x 8 k-slices of 16 dims.
// Per pair: three dots (k1.S0, k2.S0, q1.S0) + prev o2 reduced in ONE interleaved
// shfl burst; u1/u2/o1 via scalars (cross terms precomputed); one decay per pair;
// o2 = q2.S2 deferred. Owned/other state split as before.
__global__ __launch_bounds__(256, 1) void rec_kernel(float* __restrict__ out)
{
    const int blk = blockIdx.x;
    const int b   = blk >> 6;
    const int h   = (blk >> 1) & 31;
    const int vh  = blk & 1;
    const int hk  = h >> 1;

    const int tid = threadIdx.x;
    const int c2  = tid >> 3;          // column pair 0..31
    const int p   = tid & 7;           // k-slice 0..7 (16 dims)
    const bool lowp = (p < 4);

    __shared__ float sk[2][TB][8][20];
    __shared__ float sq[2][TB][8][20];
    __shared__ float sv[2][TB][64];
    __shared__ float2 sg[2][TB];
    __shared__ float2 scr[2][TB / 2];

    ull so[8], sx[8];                  // owned / other column state
#pragma unroll
    for (int i = 0; i < 8; i++) { so[i] = 0ull; sx[i] = 0ull; }

    const float* kbase = g_kn + ((size_t)(b * S_LEN) * HK + hk) * DK;
    const float* qbase = g_qn + ((size_t)(b * S_LEN) * HK + hk) * DK;
    const float* vbase = g_v  + ((size_t)(b * S_LEN) * HV + h) * DV + vh * 64;
    const float* gbase = g_gate + ((size_t)(b * S_LEN) * HV + h) * 2;
    const size_t qk_stride = (size_t)HK * DK;
    const size_t v_stride  = (size_t)HV * DV;

    auto load_batch = [&](int buf, int t0) {
#pragma unroll
        for (int rep = 0; rep < 2; rep++) {
            int i  = tid + rep * 256;
            int tt = i >> 5, j = i & 31;
            cpa16(&sk[buf][tt][j >> 2][(j & 3) * 4],
                  kbase + (size_t)(t0 + tt) * qk_stride + j * 4);
            cpa16(&sq[buf][tt][j >> 2][(j & 3) * 4],
                  qbase + (size_t)(t0 + tt) * qk_stride + j * 4);
        }
        {
            int tt = tid >> 4, j = tid & 15;
            cpa16(&sv[buf][tt][j * 4],
                  vbase + (size_t)(t0 + tt) * v_stride + j * 4);
        }
        if (tid < TB)
            cpa8(&sg[buf][tid], gbase + (size_t)(t0 + tid) * (HV * 2));
        if (tid < TB / 2)
            cpa8(&scr[buf][tid],
                 &g_cross[(size_t)(b * (S_LEN / 2) + (t0 >> 1) + tid) * HK + hk]);
        cpa_commit();
    };

    load_batch(0, 0);
    cpa_wait0();
    __syncthreads();
    int buf = 0;

    float* obase = out + ((size_t)(b * S_LEN) * HV + h) * DV + vh * 64 + c2 * 2;
    const int osel = lowp ? 0 : 1;

    float oo_m = 0.f, oo_o = 0.f;      // prev token's o2 partials (own/other)

    F4U k1A[4], k2A[4], q1A[4], k1B[4], k2B[4], q1B[4];

#define PLOAD(k1r, k2r, q1r, PP) do {                                         \
    const int _s = (PP) * 2;                                                  \
    const float* _k1 = &sk[buf][_s][p][0];                                    \
    const float* _k2 = &sk[buf][_s + 1][p][0];                                \
    const float* _q1 = &sq[buf][_s][p][0];                                    \
    _Pragma("unroll")                                                         \
    for (int i = 0; i < 4; i++) {                                             \
        k1r[i].f = *reinterpret_cast<const float4*>(_k1 + i * 4);             \
        k2r[i].f = *reinterpret_cast<const float4*>(_k2 + i * 4);             \
        q1r[i].f = *reinterpret_cast<const float4*>(_q1 + i * 4);             \
    }                                                                         \
} while (0)

#define PBODY(k1r, k2r, q1r, PP, T) do {                                      \
    const float2 ga = sg[buf][2 * (PP)];                                      \
    const float2 gb = sg[buf][2 * (PP) + 1];                                  \
    const float e1 = ga.x, b1 = ga.y, e2 = gb.x, b2 = gb.y;                   \
    const float2 cr = scr[buf][PP];                                           \
    ull A0 = 0, A1 = 0, B0 = 0, B1 = 0, C0 = 0, C1 = 0;                       \
    ull D0 = 0, D1 = 0, E0 = 0, E1 = 0, F0 = 0, F1 = 0;                       \
    _Pragma("unroll")                                                         \
    for (int i = 0; i < 4; i++) {                                             \
        FMA2(A0, k1r[i].u[0], so[2*i],   A0);                                 \
        FMA2(A1, k1r[i].u[1], so[2*i+1], A1);                                 \
        FMA2(B0, k2r[i].u[0], so[2*i],   B0);                                 \
        FMA2(B1, k2r[i].u[1], so[2*i+1], B1);                                 \
        FMA2(C0, q1r[i].u[0], so[2*i],   C0);                                 \
        FMA2(C1, q1r[i].u[1], so[2*i+1], C1);                                 \
        FMA2(D0, k1r[i].u[0], sx[2*i],   D0);                                 \
        FMA2(D1, k1r[i].u[1], sx[2*i+1], D1);                                 \
        FMA2(E0, k2r[i].u[0], sx[2*i],   E0);                                 \
        FMA2(E1, k2r[i].u[1], sx[2*i+1], E1);                                 \
        FMA2(F0, q1r[i].u[0], sx[2*i],   F0);                                 \
        FMA2(F1, q1r[i].u[1], sx[2*i+1], F1);                                 \
    }                                                                         \
    ADD2(A0, A0, A1); ADD2(B0, B0, B1); ADD2(C0, C0, C1);                     \
    ADD2(D0, D0, D1); ADD2(E0, E0, E1); ADD2(F0, F0, F1);                     \
    float2 fA = unpack2(A0), fB = unpack2(B0), fC = unpack2(C0);              \
    float2 fD = unpack2(D0), fE = unpack2(E0), fF = unpack2(F0);              \
    float Pam = fA.x + fA.y, Pbm = fB.x + fB.y, G1m = fC.x + fC.y;            \
    const float PaO = fD.x + fD.y, PbO = fE.x + fE.y, G1O = fF.x + fF.y;      \
    Pam  += __shfl_xor_sync(0xffffffffu, PaO,  4);                            \
    Pbm  += __shfl_xor_sync(0xffffffffu, PbO,  4);                            \
    G1m  += __shfl_xor_sync(0xffffffffu, G1O,  4);                            \
    oo_m += __shfl_xor_sync(0xffffffffu, oo_o, 4);                            \
    Pam  += __shfl_xor_sync(0xffffffffu, Pam,  1);                            \
    Pbm  += __shfl_xor_sync(0xffffffffu, Pbm,  1);                            \
    G1m  += __shfl_xor_sync(0xffffffffu, G1m,  1);                            \
    oo_m += __shfl_xor_sync(0xffffffffu, oo_m, 1);                            \
    Pam  += __shfl_xor_sync(0xffffffffu, Pam,  2);                            \
    Pbm  += __shfl_xor_sync(0xffffffffu, Pbm,  2);                            \
    G1m  += __shfl_xor_sync(0xffffffffu, G1m,  2);                            \
    oo_m += __shfl_xor_sync(0xffffffffu, oo_m, 2);                            \
    if ((T) != 0 && (p & 3) == 0)                                             \
        obase[(size_t)((T) - 1) * v_stride + osel] = oo_m;                    \
    const float2 v1 = *reinterpret_cast<const float2*>(&sv[buf][2*(PP)][c2*2]);   \
    const float2 v2 = *reinterpret_cast<const float2*>(&sv[buf][2*(PP)+1][c2*2]); \
    const float v1o = lowp ? v1.x : v1.y;                                     \
    const float v2o = lowp ? v2.x : v2.y;                                     \
    const float u1 = b1 * (v1o - e1 * Pam);                                   \
    const float k2S1 = e1 * Pbm + cr.x * u1;                                  \
    const float u2 = b2 * (v2o - e2 * k2S1);                                  \
    const float o1 = e1 * G1m + cr.y * u1;                                    \
    if ((p & 3) == 0)                                                         \
        obase[(size_t)(T) * v_stride + osel] = o1;                            \
    const float u1x = __shfl_xor_sync(0xffffffffu, u1, 4);                    \
    const float u2x = __shfl_xor_sync(0xffffffffu, u2, 4);                    \
    const float e12 = e1 * e2;                                                \
    const ull e12p = pack2(e12, e12);                                         \
    const float c1 = e2 * u1;                                                 \
    const ull c1p = pack2(c1, c1), u2p = pack2(u2, u2);                       \
    _Pragma("unroll")                                                         \
    for (int i = 0; i < 4; i++) {        /* owned update overlaps exchange */ \
        MUL2(so[2*i],   so[2*i],   e12p);                                     \
        MUL2(so[2*i+1], so[2*i+1], e12p);                                     \
        FMA2(so[2*i],   k1r[i].u[0], c1p, so[2*i]);                           \
        FMA2(so[2*i+1], k1r[i].u[1], c1p, so[2*i+1]);                         \
        FMA2(so[2*i],   k2r[i].u[0], u2p, so[2*i]);                           \
        FMA2(so[2*i+1], k2r[i].u[1], u2p, so[2*i+1]);                         \
    }                                                                         \
    const float c1x = e2 * u1x;                                               \
    const ull c1xp = pack2(c1x, c1x), u2xp = pack2(u2x, u2x);                 \
    _Pragma("unroll")                                                         \
    for (int i = 0; i < 4; i++) {                                             \
        MUL2(sx[2*i],   sx[2*i],   e12p);                                     \
        MUL2(sx[2*i+1], sx[2*i+1], e12p);                                     \
        FMA2(sx[2*i],   k1r[i].u[0], c1xp, sx[2*i]);                          \
        FMA2(sx[2*i+1], k1r[i].u[1], c1xp, sx[2*i+1]);                        \
        FMA2(sx[2*i],   k2r[i].u[0], u2xp, sx[2*i]);                          \
        FMA2(sx[2*i+1], k2r[i].u[1], u2xp, sx[2*i+1]);                        \
    }                                                                         \
    F4U q2r[4];                                                               \
    const float* _q2 = &sq[buf][2*(PP)+1][p][0];                              \
    _Pragma("unroll")                                                         \
    for (int i = 0; i < 4; i++)                                               \
        q2r[i].f = *reinterpret_cast<const float4*>(_q2 + i * 4);             \
    ull qa0 = 0, qa1 = 0, qb0 = 0, qb1 = 0;                                   \
    _Pragma("unroll")                                                         \
    for (int i = 0; i < 4; i++) {                                             \
        FMA2(qa0, q2r[i].u[0], so[2*i],   qa0);                               \
        FMA2(qa1, q2r[i].u[1], so[2*i+1], qa1);                               \
        FMA2(qb0, q2r[i].u[0], sx[2*i],   qb0);                               \
        FMA2(qb1, q2r[i].u[1], sx[2*i+1], qb1);                               \
    }                                                                         \
    ADD2(qa0, qa0, qa1); ADD2(qb0, qb0, qb1);                                 \
    float2 gqa = unpack2(qa0), gqb = unpack2(qb0);                            \
    oo_m = gqa.x + gqa.y;                                                     \
    oo_o = gqb.x + gqb.y;                                                     \
} while (0)

#pragma unroll 1
    for (int t0 = 0; t0 < S_LEN; t0 += TB) {
        if (t0 + TB < S_LEN) load_batch(buf ^ 1, t0 + TB);

        PLOAD(k1A, k2A, q1A, 0);
#pragma unroll 2
        for (int pp = 0; pp < TB / 2; pp += 2) {
            PLOAD(k1B, k2B, q1B, pp + 1);
            PBODY(k1A, k2A, q1A, pp, t0 + 2 * pp);
            {
                int pn = pp + 2; if (pn > TB / 2 - 1) pn = TB / 2 - 1;
                PLOAD(k1A, k2A, q1A, pn);
            }
            PBODY(k1B, k2B, q1B, pp + 1, t0 + 2 * (pp + 1));
        }

        cpa_wait0();
        __syncthreads();
        buf ^= 1;
    }

    // drain: reduce and store the final token's o2
    {
        oo_m += __shfl_xor_sync(0xffffffffu, oo_o, 4);
        oo_m += __shfl_xor_sync(0xffffffffu, oo_m, 1);
        oo_m += __shfl_xor_sync(0xffffffffu, oo_m, 2);
        if ((p & 3) == 0)
            obase[(size_t)(S_LEN - 1) * v_stride + osel] = oo_m;
    }
#undef PLOAD
#undef PBODY
}

// ---------------- launch ----------------
extern "C" void kernel_launch(void* const* d_in, const int* in_sizes, int n_in,
                              void* d_out, int out_size)
{
    const float* mixed_qkv = (const float*)d_in[0];
    const float* bvec      = (const float*)d_in[1];
    const float* avec      = (const float*)d_in[2];
    const float* convw     = (const float*)d_in[3];
    const float* dt_bias   = (const float*)d_in[4];
    const float* alog      = (const float*)d_in[5];
    float* out = (float*)d_out;

    prep_kernel<<<2048, 256>>>(mixed_qkv, convw);
    cross_kernel<<<BQ * HK * (S_LEN / 2) / 8, 256>>>();
    gate_kernel<<<NROWS * HV / 256, 256>>>(bvec, avec, dt_bias, alog);
    rec_kernel<<<BQ * HV * 2, 256>>>(out);
}